// round 7
// baseline (speedup 1.0000x reference)
#include <cuda_runtime.h>
#include <math.h>

// Problem constants (match reference setup_inputs)
#define NN 100000      // nodes
#define NE 1600000     // edges
#define NG 128         // graphs
#define INF 128
#define HF  128
#define OF  64
#define HID 10
#define NCLS 10

// ---------------- scratch (device globals; allocation-free) ----------------
__device__ __align__(128) float g_Y1[(size_t)NN * 128]; // feats @ W1, scaled by sO
__device__ __align__(128) float g_M1[(size_t)NN * 128]; // aggregated (atomics)
__device__ __align__(128) float g_Y2[(size_t)NN * 64];  // h1 @ W2, scaled by sO
__device__ __align__(128) float g_M2[(size_t)NN * 64];  // aggregated (atomics)
__device__ int   g_degO[NN];
__device__ int   g_degI[NN];
__device__ float g_sO[NN];
__device__ float g_sI[NN];
__device__ float g_pooled[NG * 64];

// ---------------- helpers ----------------
__device__ __forceinline__ void red4(float* p, float4 v) {
    asm volatile("red.global.add.v4.f32 [%0], {%1,%2,%3,%4};"
                 :: "l"(p), "f"(v.x), "f"(v.y), "f"(v.z), "f"(v.w) : "memory");
}

// ---------------- kernels ----------------
__global__ void zero_kernel() {
    size_t i = (size_t)blockIdx.x * blockDim.x + threadIdx.x;
    size_t stride = (size_t)gridDim.x * blockDim.x;
    float4 z = make_float4(0.f, 0.f, 0.f, 0.f);
    float4* m1 = (float4*)g_M1;
    float4* m2 = (float4*)g_M2;
    for (size_t k = i; k < (size_t)NN * 32; k += stride) m1[k] = z;
    for (size_t k = i; k < (size_t)NN * 16; k += stride) m2[k] = z;
    int4 zi = make_int4(0, 0, 0, 0);
    int4* dO = (int4*)g_degO;
    int4* dI = (int4*)g_degI;
    for (size_t k = i; k < NN / 4; k += stride) { dO[k] = zi; dI[k] = zi; }
}

__global__ void degree_kernel(const int* __restrict__ src, const int* __restrict__ dst) {
    int i = blockIdx.x * 256 + threadIdx.x;
    if (i < NE) {
        atomicAdd(&g_degO[src[i]], 1);
        atomicAdd(&g_degI[dst[i]], 1);
    }
}

__global__ void scale_kernel() {
    int i = blockIdx.x * 256 + threadIdx.x;
    if (i < NN) {
        g_sO[i] = rsqrtf(fmaxf((float)g_degO[i], 1.f));
        g_sI[i] = rsqrtf(fmaxf((float)g_degI[i], 1.f));
    }
}

// Register-tiled GEMM: Y[r][n] = sO[r] * sum_k A(r,k) * W[k][n]
// A(r,k) = X[r][k]                    (PRE = false)
// A(r,k) = relu(X[r][k]*sI[r]+b[k])   (PRE = true, fuses layer-1 epilogue)
// BM=128, BK=32, K=128 fixed, 256 threads, 8xTN micro-tiles.
template <int BN, bool PRE>
__device__ __forceinline__ void gemm_body(const float* __restrict__ X,
                                          const float* __restrict__ W,
                                          const float* __restrict__ bias,
                                          float* __restrict__ Y) {
    constexpr int BM = 128, BK = 32;
    constexpr int TM = 8, TN = BN / 16;
    __shared__ __align__(16) float As[BK][BM + 4];   // row stride 132 floats (16B aligned)
    __shared__ __align__(16) float Bs[BK][BN + 4];   // 132 or 68 floats   (16B aligned)

    const int tid = threadIdx.x;            // 0..255
    const int tx = tid & 15;                // 0..15
    const int ty = tid >> 4;                // 0..15
    const int row0 = blockIdx.x * BM;

    float acc[TM][TN];
#pragma unroll
    for (int i = 0; i < TM; i++)
#pragma unroll
        for (int j = 0; j < TN; j++) acc[i][j] = 0.f;

    for (int k0 = 0; k0 < 128; k0 += BK) {
        // ---- load A tile: 128x32 floats = 1024 float4, 4 per thread ----
#pragma unroll
        for (int i = 0; i < 4; i++) {
            int idx = tid + i * 256;       // 0..1023
            int r   = idx >> 3;            // 8 float4 per row
            int c4  = idx & 7;
            int grow = row0 + r;
            float4 v = make_float4(0.f, 0.f, 0.f, 0.f);
            if (grow < NN) {
                v = *(const float4*)(X + (size_t)grow * 128 + k0 + c4 * 4);
                if (PRE) {
                    float si = g_sI[grow];
                    int kb = k0 + c4 * 4;
                    v.x = fmaxf(fmaf(v.x, si, bias[kb + 0]), 0.f);
                    v.y = fmaxf(fmaf(v.y, si, bias[kb + 1]), 0.f);
                    v.z = fmaxf(fmaf(v.z, si, bias[kb + 2]), 0.f);
                    v.w = fmaxf(fmaf(v.w, si, bias[kb + 3]), 0.f);
                }
            }
            As[c4 * 4 + 0][r] = v.x;
            As[c4 * 4 + 1][r] = v.y;
            As[c4 * 4 + 2][r] = v.z;
            As[c4 * 4 + 3][r] = v.w;
        }
        // ---- load B tile: BK x BN floats ----
        constexpr int NB4 = BK * BN / 4;   // 1024 or 512
#pragma unroll
        for (int i = 0; i < NB4 / 256; i++) {
            int idx = tid + i * 256;
            int r   = idx / (BN / 4);
            int c4  = idx % (BN / 4);
            float4 v = *(const float4*)(W + (size_t)(k0 + r) * BN + c4 * 4);
            *(float4*)&Bs[r][c4 * 4] = v;
        }
        __syncthreads();
        // ---- micro-kernel ----
#pragma unroll
        for (int kk = 0; kk < BK; kk++) {
            float a[TM], b[TN];
            {
                float4 a0 = *(const float4*)&As[kk][ty * TM];
                float4 a1 = *(const float4*)&As[kk][ty * TM + 4];
                a[0] = a0.x; a[1] = a0.y; a[2] = a0.z; a[3] = a0.w;
                a[4] = a1.x; a[5] = a1.y; a[6] = a1.z; a[7] = a1.w;
            }
            {
                float4 b0 = *(const float4*)&Bs[kk][tx * TN];
                b[0] = b0.x; b[1] = b0.y; b[2] = b0.z; b[3] = b0.w;
                if (TN == 8) {
                    float4 b1 = *(const float4*)&Bs[kk][tx * TN + 4];
                    b[4] = b1.x; b[5] = b1.y; b[6] = b1.z; b[7] = b1.w;
                }
            }
#pragma unroll
            for (int i = 0; i < TM; i++)
#pragma unroll
                for (int j = 0; j < TN; j++) acc[i][j] = fmaf(a[i], b[j], acc[i][j]);
        }
        __syncthreads();
    }
    // ---- epilogue: scale by sO[row], vectorized store ----
#pragma unroll
    for (int i = 0; i < TM; i++) {
        int grow = row0 + ty * TM + i;
        if (grow < NN) {
            float so = g_sO[grow];
#pragma unroll
            for (int j = 0; j < TN; j += 4) {
                float4 v = make_float4(acc[i][j] * so, acc[i][j + 1] * so,
                                       acc[i][j + 2] * so, acc[i][j + 3] * so);
                *(float4*)(Y + (size_t)grow * BN + tx * TN + j) = v;
            }
        }
    }
}

__global__ void __launch_bounds__(256) gemm1_kernel(const float* __restrict__ feats,
                                                    const float* __restrict__ W1) {
    gemm_body<128, false>(feats, W1, nullptr, g_Y1);
}

__global__ void __launch_bounds__(256) gemm2_kernel(const float* __restrict__ W2,
                                                    const float* __restrict__ b1) {
    gemm_body<64, true>(g_M1, W2, b1, g_Y2);
}

// Edge scatter, layer 1: one warp per edge; 32 lanes = 32 float4 = 128 floats.
__global__ void __launch_bounds__(256) scatter128_kernel(const int* __restrict__ src,
                                                         const int* __restrict__ dst) {
    int warp = (blockIdx.x * 256 + threadIdx.x) >> 5;
    int lane = threadIdx.x & 31;
    if (warp >= NE) return;
    int s = src[warp];
    int d = dst[warp];
    float4 v = ((const float4*)g_Y1)[(size_t)s * 32 + lane];
    red4((float*)(((float4*)g_M1) + (size_t)d * 32 + lane), v);
}

// Edge scatter, layer 2: half-warp per edge; 16 lanes = 16 float4 = 64 floats.
__global__ void __launch_bounds__(256) scatter64_kernel(const int* __restrict__ src,
                                                        const int* __restrict__ dst) {
    int t = blockIdx.x * 256 + threadIdx.x;
    int e = t >> 4;
    int lane = t & 15;
    if (e >= NE) return;
    int s = src[e];
    int d = dst[e];
    float4 v = ((const float4*)g_Y2)[(size_t)s * 16 + lane];
    red4((float*)(((float4*)g_M2) + (size_t)d * 16 + lane), v);
}

// Block per graph; graph_ids sorted -> binary search boundaries; no atomics.
// h2 = relu(sI[n]*M2[n][c] + b2[c]); pooled = mean over nodes of graph.
__global__ void __launch_bounds__(256) pool_kernel(const int* __restrict__ gids,
                                                   const float* __restrict__ b2) {
    int g = blockIdx.x;
    int lo = 0, hi = NN;
    while (lo < hi) { int mid = (lo + hi) >> 1; if (gids[mid] < g) lo = mid + 1; else hi = mid; }
    int start = lo;
    hi = NN;
    while (lo < hi) { int mid = (lo + hi) >> 1; if (gids[mid] < g + 1) lo = mid + 1; else hi = mid; }
    int end = lo;

    int col = threadIdx.x & 63;
    int sub = threadIdx.x >> 6;   // 0..3
    float bc = b2[col];
    float acc = 0.f;
    for (int n = start + sub; n < end; n += 4) {
        float v = fmaf(g_M2[(size_t)n * 64 + col], g_sI[n], bc);
        acc += fmaxf(v, 0.f);
    }
    __shared__ float sacc[4][64];
    sacc[sub][col] = acc;
    __syncthreads();
    if (sub == 0) {
        float tot = sacc[0][col] + sacc[1][col] + sacc[2][col] + sacc[3][col];
        int cnt = end - start;
        float c = (float)(cnt > 0 ? cnt : 1);
        g_pooled[g * 64 + col] = tot / c;
    }
}

// Tiny MLP head + softmax: one block, thread per graph.
__global__ void __launch_bounds__(128) head_kernel(const float* __restrict__ fcW1,
                                                   const float* __restrict__ fcb1,
                                                   const float* __restrict__ fcW2,
                                                   const float* __restrict__ fcb2,
                                                   float* __restrict__ out) {
    __shared__ float w1s[OF * HID];
    __shared__ float w2s[HID * NCLS];
    for (int i = threadIdx.x; i < OF * HID; i += blockDim.x) w1s[i] = fcW1[i];
    for (int i = threadIdx.x; i < HID * NCLS; i += blockDim.x) w2s[i] = fcW2[i];
    __syncthreads();

    int g = threadIdx.x;
    if (g >= NG) return;
    float x[OF];
#pragma unroll
    for (int c = 0; c < OF; c++) x[c] = g_pooled[g * 64 + c];
    float z[HID];
#pragma unroll
    for (int h = 0; h < HID; h++) {
        float s = fcb1[h];
#pragma unroll
        for (int c = 0; c < OF; c++) s = fmaf(x[c], w1s[c * HID + h], s);
        z[h] = fmaxf(s, 0.f);
    }
    float o[NCLS];
    float mx = -1e30f;
#pragma unroll
    for (int k = 0; k < NCLS; k++) {
        float s = fcb2[k];
#pragma unroll
        for (int h = 0; h < HID; h++) s = fmaf(z[h], w2s[h * NCLS + k], s);
        o[k] = s;
        mx = fmaxf(mx, s);
    }
    float sum = 0.f;
#pragma unroll
    for (int k = 0; k < NCLS; k++) { o[k] = expf(o[k] - mx); sum += o[k]; }
    float inv = 1.f / sum;
#pragma unroll
    for (int k = 0; k < NCLS; k++) out[g * NCLS + k] = o[k] * inv;
}

// ---------------- launch ----------------
extern "C" void kernel_launch(void* const* d_in, const int* in_sizes, int n_in,
                              void* d_out, int out_size) {
    const float* feats = (const float*)d_in[0];
    const int*   src   = (const int*)d_in[1];
    const int*   dst   = (const int*)d_in[2];
    const int*   gids  = (const int*)d_in[3];
    const float* W1    = (const float*)d_in[4];
    const float* b1    = (const float*)d_in[5];
    const float* W2    = (const float*)d_in[6];
    const float* b2    = (const float*)d_in[7];
    const float* fcW1  = (const float*)d_in[8];
    const float* fcb1  = (const float*)d_in[9];
    const float* fcW2  = (const float*)d_in[10];
    const float* fcb2  = (const float*)d_in[11];
    float* out = (float*)d_out;

    zero_kernel<<<4096, 256>>>();
    degree_kernel<<<(NE + 255) / 256, 256>>>(src, dst);
    scale_kernel<<<(NN + 255) / 256, 256>>>();

    // Layer 1: Y1 = sO .* (feats @ W1); M1 = A Y1
    gemm1_kernel<<<(NN + 127) / 128, 256>>>(feats, W1);
    scatter128_kernel<<<(NE * 32 + 255) / 256, 256>>>(src, dst);

    // Layer 2: h1 = relu(sI .* M1 + b1) fused into A-load; Y2 = sO .* (h1 @ W2); M2 = A Y2
    gemm2_kernel<<<(NN + 127) / 128, 256>>>(W2, b1);
    scatter64_kernel<<<(NE * 16 + 255) / 256, 256>>>(src, dst);

    // Pool (applies relu(sI .* M2 + b2) and per-graph mean) + head MLP + softmax
    pool_kernel<<<NG, 256>>>(gids, b2);
    head_kernel<<<1, 128>>>(fcW1, fcb1, fcW2, fcb2, out);
}

// round 9
// speedup vs baseline: 1.0102x; 1.0102x over previous
#include <cuda_runtime.h>
#include <math.h>

// Problem constants (match reference setup_inputs)
#define NN 100000      // nodes
#define NE 1600000     // edges
#define NG 128         // graphs
#define INF 128
#define HF  128
#define OF  64
#define HID 10
#define NCLS 10

// ---------------- scratch (device globals; allocation-free) ----------------
__device__ __align__(128) float g_Y1[(size_t)NN * 128]; // feats @ W1, scaled by sO
__device__ __align__(128) float g_M1[(size_t)NN * 128]; // aggregated (atomics)
__device__ __align__(128) float g_Y2[(size_t)NN * 64];  // h1 @ W2, scaled by sO
__device__ __align__(128) float g_M2[(size_t)NN * 64];  // aggregated (atomics)
__device__ int   g_degO[NN];
__device__ int   g_degI[NN];
__device__ float g_sO[NN];
__device__ float g_sI[NN];
__device__ float g_pooled[NG * 64];

// ---------------- helpers ----------------
__device__ __forceinline__ void red4(float* p, float4 v) {
    asm volatile("red.global.add.v4.f32 [%0], {%1,%2,%3,%4};"
                 :: "l"(p), "f"(v.x), "f"(v.y), "f"(v.z), "f"(v.w) : "memory");
}

// ---------------- kernels ----------------
__global__ void zero_kernel() {
    size_t i = (size_t)blockIdx.x * blockDim.x + threadIdx.x;
    size_t stride = (size_t)gridDim.x * blockDim.x;
    float4 z = make_float4(0.f, 0.f, 0.f, 0.f);
    float4* m1 = (float4*)g_M1;
    float4* m2 = (float4*)g_M2;
    for (size_t k = i; k < (size_t)NN * 32; k += stride) m1[k] = z;
    for (size_t k = i; k < (size_t)NN * 16; k += stride) m2[k] = z;
    int4 zi = make_int4(0, 0, 0, 0);
    int4* dO = (int4*)g_degO;
    int4* dI = (int4*)g_degI;
    for (size_t k = i; k < NN / 4; k += stride) { dO[k] = zi; dI[k] = zi; }
}

__global__ void degree_kernel(const int* __restrict__ src, const int* __restrict__ dst) {
    int i = blockIdx.x * 256 + threadIdx.x;
    if (i < NE) {
        atomicAdd(&g_degO[src[i]], 1);
        atomicAdd(&g_degI[dst[i]], 1);
    }
}

__global__ void scale_kernel() {
    int i = blockIdx.x * 256 + threadIdx.x;
    if (i < NN) {
        g_sO[i] = rsqrtf(fmaxf((float)g_degO[i], 1.f));
        g_sI[i] = rsqrtf(fmaxf((float)g_degI[i], 1.f));
    }
}

// Register-tiled GEMM: Y[r][n] = sO[r] * sum_k A(r,k) * W[k][n]
// A(r,k) = X[r][k]                    (PRE = false)
// A(r,k) = relu(X[r][k]*sI[r]+b[k])   (PRE = true, fuses layer-1 epilogue)
// BM=128, BK=32, K=128 fixed, 256 threads, 8xTN micro-tiles.
template <int BN, bool PRE>
__device__ __forceinline__ void gemm_body(const float* __restrict__ X,
                                          const float* __restrict__ W,
                                          const float* __restrict__ bias,
                                          float* __restrict__ Y) {
    constexpr int BM = 128, BK = 32;
    constexpr int TM = 8, TN = BN / 16;
    __shared__ __align__(16) float As[BK][BM + 4];   // row stride 132 floats (16B aligned)
    __shared__ __align__(16) float Bs[BK][BN + 4];   // 132 or 68 floats   (16B aligned)

    const int tid = threadIdx.x;            // 0..255
    const int tx = tid & 15;                // 0..15
    const int ty = tid >> 4;                // 0..15
    const int row0 = blockIdx.x * BM;

    float acc[TM][TN];
#pragma unroll
    for (int i = 0; i < TM; i++)
#pragma unroll
        for (int j = 0; j < TN; j++) acc[i][j] = 0.f;

    for (int k0 = 0; k0 < 128; k0 += BK) {
        // ---- load A tile: 128x32 floats = 1024 float4, 4 per thread ----
#pragma unroll
        for (int i = 0; i < 4; i++) {
            int idx = tid + i * 256;       // 0..1023
            int r   = idx >> 3;            // 8 float4 per row
            int c4  = idx & 7;
            int grow = row0 + r;
            float4 v = make_float4(0.f, 0.f, 0.f, 0.f);
            if (grow < NN) {
                v = *(const float4*)(X + (size_t)grow * 128 + k0 + c4 * 4);
                if (PRE) {
                    float si = g_sI[grow];
                    int kb = k0 + c4 * 4;
                    v.x = fmaxf(fmaf(v.x, si, bias[kb + 0]), 0.f);
                    v.y = fmaxf(fmaf(v.y, si, bias[kb + 1]), 0.f);
                    v.z = fmaxf(fmaf(v.z, si, bias[kb + 2]), 0.f);
                    v.w = fmaxf(fmaf(v.w, si, bias[kb + 3]), 0.f);
                }
            }
            As[c4 * 4 + 0][r] = v.x;
            As[c4 * 4 + 1][r] = v.y;
            As[c4 * 4 + 2][r] = v.z;
            As[c4 * 4 + 3][r] = v.w;
        }
        // ---- load B tile: BK x BN floats ----
        constexpr int NB4 = BK * BN / 4;   // 1024 or 512
#pragma unroll
        for (int i = 0; i < NB4 / 256; i++) {
            int idx = tid + i * 256;
            int r   = idx / (BN / 4);
            int c4  = idx % (BN / 4);
            float4 v = *(const float4*)(W + (size_t)(k0 + r) * BN + c4 * 4);
            *(float4*)&Bs[r][c4 * 4] = v;
        }
        __syncthreads();
        // ---- micro-kernel ----
#pragma unroll
        for (int kk = 0; kk < BK; kk++) {
            float a[TM], b[TN];
            {
                float4 a0 = *(const float4*)&As[kk][ty * TM];
                float4 a1 = *(const float4*)&As[kk][ty * TM + 4];
                a[0] = a0.x; a[1] = a0.y; a[2] = a0.z; a[3] = a0.w;
                a[4] = a1.x; a[5] = a1.y; a[6] = a1.z; a[7] = a1.w;
            }
            {
                float4 b0 = *(const float4*)&Bs[kk][tx * TN];
                b[0] = b0.x; b[1] = b0.y; b[2] = b0.z; b[3] = b0.w;
                if (TN == 8) {
                    float4 b1 = *(const float4*)&Bs[kk][tx * TN + 4];
                    b[4] = b1.x; b[5] = b1.y; b[6] = b1.z; b[7] = b1.w;
                }
            }
#pragma unroll
            for (int i = 0; i < TM; i++)
#pragma unroll
                for (int j = 0; j < TN; j++) acc[i][j] = fmaf(a[i], b[j], acc[i][j]);
        }
        __syncthreads();
    }
    // ---- epilogue: scale by sO[row], vectorized store ----
#pragma unroll
    for (int i = 0; i < TM; i++) {
        int grow = row0 + ty * TM + i;
        if (grow < NN) {
            float so = g_sO[grow];
#pragma unroll
            for (int j = 0; j < TN; j += 4) {
                float4 v = make_float4(acc[i][j] * so, acc[i][j + 1] * so,
                                       acc[i][j + 2] * so, acc[i][j + 3] * so);
                *(float4*)(Y + (size_t)grow * BN + tx * TN + j) = v;
            }
        }
    }
}

__global__ void __launch_bounds__(256) gemm1_kernel(const float* __restrict__ feats,
                                                    const float* __restrict__ W1) {
    gemm_body<128, false>(feats, W1, nullptr, g_Y1);
}

__global__ void __launch_bounds__(256) gemm2_kernel(const float* __restrict__ W2,
                                                    const float* __restrict__ b1) {
    gemm_body<64, true>(g_M1, W2, b1, g_Y2);
}

// Edge scatter, layer 1: one warp per edge; 32 lanes = 32 float4 = 128 floats.
__global__ void __launch_bounds__(256) scatter128_kernel(const int* __restrict__ src,
                                                         const int* __restrict__ dst) {
    int warp = (blockIdx.x * 256 + threadIdx.x) >> 5;
    int lane = threadIdx.x & 31;
    if (warp >= NE) return;
    int s = src[warp];
    int d = dst[warp];
    float4 v = ((const float4*)g_Y1)[(size_t)s * 32 + lane];
    red4((float*)(((float4*)g_M1) + (size_t)d * 32 + lane), v);
}

// Edge scatter, layer 2: half-warp per edge; 16 lanes = 16 float4 = 64 floats.
__global__ void __launch_bounds__(256) scatter64_kernel(const int* __restrict__ src,
                                                        const int* __restrict__ dst) {
    int t = blockIdx.x * 256 + threadIdx.x;
    int e = t >> 4;
    int lane = t & 15;
    if (e >= NE) return;
    int s = src[e];
    int d = dst[e];
    float4 v = ((const float4*)g_Y2)[(size_t)s * 16 + lane];
    red4((float*)(((float4*)g_M2) + (size_t)d * 16 + lane), v);
}

// Block per graph; graph_ids sorted -> binary search boundaries; no atomics.
// h2 = relu(sI[n]*M2[n][c] + b2[c]); pooled = mean over nodes of graph.
__global__ void __launch_bounds__(256) pool_kernel(const int* __restrict__ gids,
                                                   const float* __restrict__ b2) {
    int g = blockIdx.x;
    int lo = 0, hi = NN;
    while (lo < hi) { int mid = (lo + hi) >> 1; if (gids[mid] < g) lo = mid + 1; else hi = mid; }
    int start = lo;
    hi = NN;
    while (lo < hi) { int mid = (lo + hi) >> 1; if (gids[mid] < g + 1) lo = mid + 1; else hi = mid; }
    int end = lo;

    int col = threadIdx.x & 63;
    int sub = threadIdx.x >> 6;   // 0..3
    float bc = b2[col];
    float acc = 0.f;
    for (int n = start + sub; n < end; n += 4) {
        float v = fmaf(g_M2[(size_t)n * 64 + col], g_sI[n], bc);
        acc += fmaxf(v, 0.f);
    }
    __shared__ float sacc[4][64];
    sacc[sub][col] = acc;
    __syncthreads();
    if (sub == 0) {
        float tot = sacc[0][col] + sacc[1][col] + sacc[2][col] + sacc[3][col];
        int cnt = end - start;
        float c = (float)(cnt > 0 ? cnt : 1);
        g_pooled[g * 64 + col] = tot / c;
    }
}

// Tiny MLP head + softmax: one block, thread per graph.
__global__ void __launch_bounds__(128) head_kernel(const float* __restrict__ fcW1,
                                                   const float* __restrict__ fcb1,
                                                   const float* __restrict__ fcW2,
                                                   const float* __restrict__ fcb2,
                                                   float* __restrict__ out) {
    __shared__ float w1s[OF * HID];
    __shared__ float w2s[HID * NCLS];
    for (int i = threadIdx.x; i < OF * HID; i += blockDim.x) w1s[i] = fcW1[i];
    for (int i = threadIdx.x; i < HID * NCLS; i += blockDim.x) w2s[i] = fcW2[i];
    __syncthreads();

    int g = threadIdx.x;
    if (g >= NG) return;
    float x[OF];
#pragma unroll
    for (int c = 0; c < OF; c++) x[c] = g_pooled[g * 64 + c];
    float z[HID];
#pragma unroll
    for (int h = 0; h < HID; h++) {
        float s = fcb1[h];
#pragma unroll
        for (int c = 0; c < OF; c++) s = fmaf(x[c], w1s[c * HID + h], s);
        z[h] = fmaxf(s, 0.f);
    }
    float o[NCLS];
    float mx = -1e30f;
#pragma unroll
    for (int k = 0; k < NCLS; k++) {
        float s = fcb2[k];
#pragma unroll
        for (int h = 0; h < HID; h++) s = fmaf(z[h], w2s[h * NCLS + k], s);
        o[k] = s;
        mx = fmaxf(mx, s);
    }
    float sum = 0.f;
#pragma unroll
    for (int k = 0; k < NCLS; k++) { o[k] = expf(o[k] - mx); sum += o[k]; }
    float inv = 1.f / sum;
#pragma unroll
    for (int k = 0; k < NCLS; k++) out[g * NCLS + k] = o[k] * inv;
}

// ---------------- launch ----------------
extern "C" void kernel_launch(void* const* d_in, const int* in_sizes, int n_in,
                              void* d_out, int out_size) {
    const float* feats = (const float*)d_in[0];
    const int*   src   = (const int*)d_in[1];
    const int*   dst   = (const int*)d_in[2];
    const int*   gids  = (const int*)d_in[3];
    const float* W1    = (const float*)d_in[4];
    const float* b1    = (const float*)d_in[5];
    const float* W2    = (const float*)d_in[6];
    const float* b2    = (const float*)d_in[7];
    const float* fcW1  = (const float*)d_in[8];
    const float* fcb1  = (const float*)d_in[9];
    const float* fcW2  = (const float*)d_in[10];
    const float* fcb2  = (const float*)d_in[11];
    float* out = (float*)d_out;

    zero_kernel<<<4096, 256>>>();
    degree_kernel<<<(NE + 255) / 256, 256>>>(src, dst);
    scale_kernel<<<(NN + 255) / 256, 256>>>();

    // Layer 1: Y1 = sO .* (feats @ W1); M1 = A Y1
    gemm1_kernel<<<(NN + 127) / 128, 256>>>(feats, W1);
    scatter128_kernel<<<(NE * 32 + 255) / 256, 256>>>(src, dst);

    // Layer 2: h1 = relu(sI .* M1 + b1) fused into A-load; Y2 = sO .* (h1 @ W2); M2 = A Y2
    gemm2_kernel<<<(NN + 127) / 128, 256>>>(W2, b1);
    scatter64_kernel<<<(NE * 16 + 255) / 256, 256>>>(src, dst);

    // Pool (applies relu(sI .* M2 + b2) and per-graph mean) + head MLP + softmax
    pool_kernel<<<NG, 256>>>(gids, b2);
    head_kernel<<<1, 128>>>(fcW1, fcb1, fcW2, fcb2, out);
}

// round 10
// speedup vs baseline: 1.0808x; 1.0699x over previous
#include <cuda_runtime.h>
#include <mma.h>
#include <math.h>

using namespace nvcuda;

// Problem constants (match reference setup_inputs)
#define NN 100000      // nodes
#define NE 1600000     // edges
#define NG 128         // graphs
#define INF 128
#define HF  128
#define OF  64
#define HID 10
#define NCLS 10

// ---------------- scratch (device globals; allocation-free) ----------------
__device__ __align__(128) float g_Y1[(size_t)NN * 128]; // feats @ W1 (unscaled)
__device__ __align__(128) float g_M1[(size_t)NN * 128]; // aggregated sum sO[s]*Y1[s]
__device__ __align__(128) float g_Y2[(size_t)NN * 64];  // h1 @ W2 (unscaled)
__device__ __align__(128) float g_M2[(size_t)NN * 64];  // aggregated sum sO[s]*Y2[s]
__device__ int   g_degO[NN];
__device__ int   g_degI[NN];
__device__ float g_sO[NN];
__device__ float g_sI[NN];
__device__ int   g_rowoff[NN + 1];   // CSR row offsets (by dst)
__device__ int   g_cursor[NN];       // fill cursors
__device__ int   g_csrc[NE];         // CSR column indices = src per dst-sorted edge
__device__ float g_pooled[NG * 64];

// ---------------- setup kernels ----------------
__global__ void zero_deg_kernel() {
    int i = blockIdx.x * 256 + threadIdx.x;
    if (i < NN) { g_degO[i] = 0; g_degI[i] = 0; }
}

__global__ void degree_kernel(const int* __restrict__ src, const int* __restrict__ dst) {
    int i = blockIdx.x * 256 + threadIdx.x;
    if (i < NE) {
        atomicAdd(&g_degO[src[i]], 1);
        atomicAdd(&g_degI[dst[i]], 1);
    }
}

__global__ void scale_kernel() {
    int i = blockIdx.x * 256 + threadIdx.x;
    if (i < NN) {
        g_sO[i] = rsqrtf(fmaxf((float)g_degO[i], 1.f));
        g_sI[i] = rsqrtf(fmaxf((float)g_degI[i], 1.f));
    }
}

// Exclusive prefix sum of g_degI -> g_rowoff / g_cursor. One block, 1024 threads.
__global__ void __launch_bounds__(1024) scan_kernel() {
    const int CH = (NN + 1023) / 1024;   // 98
    int t = threadIdx.x;
    int base = t * CH;
    int s = 0;
    for (int i = 0; i < CH; i++) {
        int idx = base + i;
        if (idx < NN) s += g_degI[idx];
    }
    __shared__ int ps[1024];
    ps[t] = s;
    __syncthreads();
    // Kogge-Stone inclusive scan
    for (int off = 1; off < 1024; off <<= 1) {
        int v = (t >= off) ? ps[t - off] : 0;
        __syncthreads();
        ps[t] += v;
        __syncthreads();
    }
    int ex = (t == 0) ? 0 : ps[t - 1];
    for (int i = 0; i < CH; i++) {
        int idx = base + i;
        if (idx < NN) {
            g_rowoff[idx] = ex;
            g_cursor[idx] = ex;
            ex += g_degI[idx];
        }
    }
    if (t == 1023) g_rowoff[NN] = ps[1023];
}

__global__ void fill_kernel(const int* __restrict__ src, const int* __restrict__ dst) {
    int e = blockIdx.x * 256 + threadIdx.x;
    if (e < NE) {
        int d = dst[e];
        int p = atomicAdd(&g_cursor[d], 1);
        g_csrc[p] = src[e];
    }
}

// ---------------- tf32 WMMA GEMMs ----------------
// Y1[100000 x 128] = feats[100000 x 128] @ W1[128 x 128]   (no scaling)
__global__ void __launch_bounds__(256) gemm1_kernel(const float* __restrict__ X,
                                                    const float* __restrict__ W) {
    __shared__ __align__(16) float As[128][36];
    __shared__ __align__(16) float Bs[32][132];
    const int tid = threadIdx.x;
    const int wid = tid >> 5;
    const int wm = wid & 3;        // 0..3  -> rows wm*32
    const int wn = wid >> 2;       // 0..1  -> cols wn*64
    const int row0 = blockIdx.x * 128;

    wmma::fragment<wmma::accumulator, 16, 16, 8, float> acc[2][4];
#pragma unroll
    for (int mi = 0; mi < 2; mi++)
#pragma unroll
        for (int nj = 0; nj < 4; nj++) wmma::fill_fragment(acc[mi][nj], 0.f);

    for (int k0 = 0; k0 < 128; k0 += 32) {
        // A tile: 128x32 floats = 1024 float4
#pragma unroll
        for (int i = 0; i < 4; i++) {
            int idx = tid + i * 256;
            int r = idx >> 3;
            int c4 = idx & 7;
            int g = row0 + r;
            float4 v = make_float4(0.f, 0.f, 0.f, 0.f);
            if (g < NN) v = *(const float4*)(X + (size_t)g * 128 + k0 + c4 * 4);
            *(float4*)&As[r][c4 * 4] = v;
        }
        // B tile: 32x128 floats
#pragma unroll
        for (int i = 0; i < 4; i++) {
            int idx = tid + i * 256;
            int r = idx >> 5;
            int c4 = idx & 31;
            *(float4*)&Bs[r][c4 * 4] = *(const float4*)(W + (size_t)(k0 + r) * 128 + c4 * 4);
        }
        __syncthreads();
#pragma unroll
        for (int kk = 0; kk < 32; kk += 8) {
            wmma::fragment<wmma::matrix_a, 16, 16, 8, wmma::precision::tf32, wmma::row_major> a0, a1;
            wmma::load_matrix_sync(a0, &As[wm * 32][kk], 36);
            wmma::load_matrix_sync(a1, &As[wm * 32 + 16][kk], 36);
#pragma unroll
            for (int e = 0; e < a0.num_elements; e++) {
                a0.x[e] = wmma::__float_to_tf32(a0.x[e]);
                a1.x[e] = wmma::__float_to_tf32(a1.x[e]);
            }
#pragma unroll
            for (int nj = 0; nj < 4; nj++) {
                wmma::fragment<wmma::matrix_b, 16, 16, 8, wmma::precision::tf32, wmma::row_major> b;
                wmma::load_matrix_sync(b, &Bs[kk][wn * 64 + nj * 16], 132);
#pragma unroll
                for (int e = 0; e < b.num_elements; e++) b.x[e] = wmma::__float_to_tf32(b.x[e]);
                wmma::mma_sync(acc[0][nj], a0, b, acc[0][nj]);
                wmma::mma_sync(acc[1][nj], a1, b, acc[1][nj]);
            }
        }
        __syncthreads();
    }
#pragma unroll
    for (int mi = 0; mi < 2; mi++) {
        int r = row0 + wm * 32 + mi * 16;
        if (r < NN) {
#pragma unroll
            for (int nj = 0; nj < 4; nj++)
                wmma::store_matrix_sync(g_Y1 + (size_t)r * 128 + wn * 64 + nj * 16,
                                        acc[mi][nj], 128, wmma::mem_row_major);
        }
    }
}

// Y2[100000 x 64] = relu(sI .* M1 + b1) @ W2[128 x 64]   (PRE fused into A load)
__global__ void __launch_bounds__(256) gemm2_kernel(const float* __restrict__ W,
                                                    const float* __restrict__ bias) {
    __shared__ __align__(16) float As[128][36];
    __shared__ __align__(16) float Bs[32][68];
    const int tid = threadIdx.x;
    const int wid = tid >> 5;
    const int wm = wid & 3;        // rows wm*32
    const int wn = wid >> 2;       // cols wn*32
    const int row0 = blockIdx.x * 128;

    wmma::fragment<wmma::accumulator, 16, 16, 8, float> acc[2][2];
#pragma unroll
    for (int mi = 0; mi < 2; mi++)
#pragma unroll
        for (int nj = 0; nj < 2; nj++) wmma::fill_fragment(acc[mi][nj], 0.f);

    for (int k0 = 0; k0 < 128; k0 += 32) {
#pragma unroll
        for (int i = 0; i < 4; i++) {
            int idx = tid + i * 256;
            int r = idx >> 3;
            int c4 = idx & 7;
            int g = row0 + r;
            float4 v = make_float4(0.f, 0.f, 0.f, 0.f);
            if (g < NN) {
                v = *(const float4*)(g_M1 + (size_t)g * 128 + k0 + c4 * 4);
                float si = g_sI[g];
                int kb = k0 + c4 * 4;
                v.x = fmaxf(fmaf(v.x, si, bias[kb + 0]), 0.f);
                v.y = fmaxf(fmaf(v.y, si, bias[kb + 1]), 0.f);
                v.z = fmaxf(fmaf(v.z, si, bias[kb + 2]), 0.f);
                v.w = fmaxf(fmaf(v.w, si, bias[kb + 3]), 0.f);
            }
            *(float4*)&As[r][c4 * 4] = v;
        }
        // B tile: 32x64 floats = 512 float4
#pragma unroll
        for (int i = 0; i < 2; i++) {
            int idx = tid + i * 256;
            int r = idx >> 4;
            int c4 = idx & 15;
            *(float4*)&Bs[r][c4 * 4] = *(const float4*)(W + (size_t)(k0 + r) * 64 + c4 * 4);
        }
        __syncthreads();
#pragma unroll
        for (int kk = 0; kk < 32; kk += 8) {
            wmma::fragment<wmma::matrix_a, 16, 16, 8, wmma::precision::tf32, wmma::row_major> a0, a1;
            wmma::load_matrix_sync(a0, &As[wm * 32][kk], 36);
            wmma::load_matrix_sync(a1, &As[wm * 32 + 16][kk], 36);
#pragma unroll
            for (int e = 0; e < a0.num_elements; e++) {
                a0.x[e] = wmma::__float_to_tf32(a0.x[e]);
                a1.x[e] = wmma::__float_to_tf32(a1.x[e]);
            }
#pragma unroll
            for (int nj = 0; nj < 2; nj++) {
                wmma::fragment<wmma::matrix_b, 16, 16, 8, wmma::precision::tf32, wmma::row_major> b;
                wmma::load_matrix_sync(b, &Bs[kk][wn * 32 + nj * 16], 68);
#pragma unroll
                for (int e = 0; e < b.num_elements; e++) b.x[e] = wmma::__float_to_tf32(b.x[e]);
                wmma::mma_sync(acc[0][nj], a0, b, acc[0][nj]);
                wmma::mma_sync(acc[1][nj], a1, b, acc[1][nj]);
            }
        }
        __syncthreads();
    }
#pragma unroll
    for (int mi = 0; mi < 2; mi++) {
        int r = row0 + wm * 32 + mi * 16;
        if (r < NN) {
#pragma unroll
            for (int nj = 0; nj < 2; nj++)
                wmma::store_matrix_sync(g_Y2 + (size_t)r * 64 + wn * 32 + nj * 16,
                                        acc[mi][nj], 64, wmma::mem_row_major);
        }
    }
}

// ---------------- CSR gather aggregation (no atomics) ----------------
// Layer 1: warp per node; lane = float4 column (32 x 16B = 128 floats).
// M1[n] = sum_{e in in(n)} sO[src_e] * Y1[src_e]
__global__ void __launch_bounds__(256) gather128_kernel() {
    int n = (blockIdx.x * 256 + threadIdx.x) >> 5;
    int lane = threadIdx.x & 31;
    if (n >= NN) return;
    int j = g_rowoff[n];
    int end = g_rowoff[n + 1];
    const float4* Y = (const float4*)g_Y1;
    float4 acc = make_float4(0.f, 0.f, 0.f, 0.f);
    for (; j + 3 < end; j += 4) {
        int s0 = g_csrc[j], s1 = g_csrc[j + 1], s2 = g_csrc[j + 2], s3 = g_csrc[j + 3];
        float c0 = g_sO[s0], c1 = g_sO[s1], c2 = g_sO[s2], c3 = g_sO[s3];
        float4 v0 = Y[(size_t)s0 * 32 + lane];
        float4 v1 = Y[(size_t)s1 * 32 + lane];
        float4 v2 = Y[(size_t)s2 * 32 + lane];
        float4 v3 = Y[(size_t)s3 * 32 + lane];
        acc.x += c0 * v0.x + c1 * v1.x + c2 * v2.x + c3 * v3.x;
        acc.y += c0 * v0.y + c1 * v1.y + c2 * v2.y + c3 * v3.y;
        acc.z += c0 * v0.z + c1 * v1.z + c2 * v2.z + c3 * v3.z;
        acc.w += c0 * v0.w + c1 * v1.w + c2 * v2.w + c3 * v3.w;
    }
    for (; j < end; j++) {
        int s = g_csrc[j];
        float c = g_sO[s];
        float4 v = Y[(size_t)s * 32 + lane];
        acc.x += c * v.x; acc.y += c * v.y; acc.z += c * v.z; acc.w += c * v.w;
    }
    ((float4*)g_M1)[(size_t)n * 32 + lane] = acc;
}

// Layer 2: half-warp per node; lane = float4 column (16 x 16B = 64 floats).
__global__ void __launch_bounds__(256) gather64_kernel() {
    int t = blockIdx.x * 256 + threadIdx.x;
    int n = t >> 4;
    int lane = t & 15;
    if (n >= NN) return;
    int j = g_rowoff[n];
    int end = g_rowoff[n + 1];
    const float4* Y = (const float4*)g_Y2;
    float4 acc = make_float4(0.f, 0.f, 0.f, 0.f);
    for (; j + 3 < end; j += 4) {
        int s0 = g_csrc[j], s1 = g_csrc[j + 1], s2 = g_csrc[j + 2], s3 = g_csrc[j + 3];
        float c0 = g_sO[s0], c1 = g_sO[s1], c2 = g_sO[s2], c3 = g_sO[s3];
        float4 v0 = Y[(size_t)s0 * 16 + lane];
        float4 v1 = Y[(size_t)s1 * 16 + lane];
        float4 v2 = Y[(size_t)s2 * 16 + lane];
        float4 v3 = Y[(size_t)s3 * 16 + lane];
        acc.x += c0 * v0.x + c1 * v1.x + c2 * v2.x + c3 * v3.x;
        acc.y += c0 * v0.y + c1 * v1.y + c2 * v2.y + c3 * v3.y;
        acc.z += c0 * v0.z + c1 * v1.z + c2 * v2.z + c3 * v3.z;
        acc.w += c0 * v0.w + c1 * v1.w + c2 * v2.w + c3 * v3.w;
    }
    for (; j < end; j++) {
        int s = g_csrc[j];
        float c = g_sO[s];
        float4 v = Y[(size_t)s * 16 + lane];
        acc.x += c * v.x; acc.y += c * v.y; acc.z += c * v.z; acc.w += c * v.w;
    }
    ((float4*)g_M2)[(size_t)n * 16 + lane] = acc;
}

// ---------------- pooling + head (unchanged) ----------------
__global__ void __launch_bounds__(256) pool_kernel(const int* __restrict__ gids,
                                                   const float* __restrict__ b2) {
    int g = blockIdx.x;
    int lo = 0, hi = NN;
    while (lo < hi) { int mid = (lo + hi) >> 1; if (gids[mid] < g) lo = mid + 1; else hi = mid; }
    int start = lo;
    hi = NN;
    while (lo < hi) { int mid = (lo + hi) >> 1; if (gids[mid] < g + 1) lo = mid + 1; else hi = mid; }
    int end = lo;

    int col = threadIdx.x & 63;
    int sub = threadIdx.x >> 6;   // 0..3
    float bc = b2[col];
    float acc = 0.f;
    for (int n = start + sub; n < end; n += 4) {
        float v = fmaf(g_M2[(size_t)n * 64 + col], g_sI[n], bc);
        acc += fmaxf(v, 0.f);
    }
    __shared__ float sacc[4][64];
    sacc[sub][col] = acc;
    __syncthreads();
    if (sub == 0) {
        float tot = sacc[0][col] + sacc[1][col] + sacc[2][col] + sacc[3][col];
        int cnt = end - start;
        float c = (float)(cnt > 0 ? cnt : 1);
        g_pooled[g * 64 + col] = tot / c;
    }
}

__global__ void __launch_bounds__(128) head_kernel(const float* __restrict__ fcW1,
                                                   const float* __restrict__ fcb1,
                                                   const float* __restrict__ fcW2,
                                                   const float* __restrict__ fcb2,
                                                   float* __restrict__ out) {
    __shared__ float w1s[OF * HID];
    __shared__ float w2s[HID * NCLS];
    for (int i = threadIdx.x; i < OF * HID; i += blockDim.x) w1s[i] = fcW1[i];
    for (int i = threadIdx.x; i < HID * NCLS; i += blockDim.x) w2s[i] = fcW2[i];
    __syncthreads();

    int g = threadIdx.x;
    if (g >= NG) return;
    float x[OF];
#pragma unroll
    for (int c = 0; c < OF; c++) x[c] = g_pooled[g * 64 + c];
    float z[HID];
#pragma unroll
    for (int h = 0; h < HID; h++) {
        float s = fcb1[h];
#pragma unroll
        for (int c = 0; c < OF; c++) s = fmaf(x[c], w1s[c * HID + h], s);
        z[h] = fmaxf(s, 0.f);
    }
    float o[NCLS];
    float mx = -1e30f;
#pragma unroll
    for (int k = 0; k < NCLS; k++) {
        float s = fcb2[k];
#pragma unroll
        for (int h = 0; h < HID; h++) s = fmaf(z[h], w2s[h * NCLS + k], s);
        o[k] = s;
        mx = fmaxf(mx, s);
    }
    float sum = 0.f;
#pragma unroll
    for (int k = 0; k < NCLS; k++) { o[k] = expf(o[k] - mx); sum += o[k]; }
    float inv = 1.f / sum;
#pragma unroll
    for (int k = 0; k < NCLS; k++) out[g * NCLS + k] = o[k] * inv;
}

// ---------------- launch ----------------
extern "C" void kernel_launch(void* const* d_in, const int* in_sizes, int n_in,
                              void* d_out, int out_size) {
    const float* feats = (const float*)d_in[0];
    const int*   src   = (const int*)d_in[1];
    const int*   dst   = (const int*)d_in[2];
    const int*   gids  = (const int*)d_in[3];
    const float* W1    = (const float*)d_in[4];
    const float* b1    = (const float*)d_in[5];
    const float* W2    = (const float*)d_in[6];
    const float* b2    = (const float*)d_in[7];
    const float* fcW1  = (const float*)d_in[8];
    const float* fcb1  = (const float*)d_in[9];
    const float* fcW2  = (const float*)d_in[10];
    const float* fcb2  = (const float*)d_in[11];
    float* out = (float*)d_out;

    // Degrees, normalization scales, CSR build (dst-sorted)
    zero_deg_kernel<<<(NN + 255) / 256, 256>>>();
    degree_kernel<<<(NE + 255) / 256, 256>>>(src, dst);
    scale_kernel<<<(NN + 255) / 256, 256>>>();
    scan_kernel<<<1, 1024>>>();
    fill_kernel<<<(NE + 255) / 256, 256>>>(src, dst);

    // Layer 1: Y1 = feats @ W1 (tf32);  M1[n] = sum sO[s] * Y1[s]
    gemm1_kernel<<<(NN + 127) / 128, 256>>>(feats, W1);
    gather128_kernel<<<(NN * 32 + 255) / 256, 256>>>();

    // Layer 2: A = relu(sI .* M1 + b1) fused; Y2 = A @ W2 (tf32); M2[n] = sum sO[s] * Y2[s]
    gemm2_kernel<<<(NN + 127) / 128, 256>>>(W2, b1);
    gather64_kernel<<<(NN * 16 + 255) / 256, 256>>>();

    // Pool (relu(sI .* M2 + b2), per-graph mean) + head MLP + softmax
    pool_kernel<<<NG, 256>>>(gids, b2);
    head_kernel<<<1, 128>>>(fcW1, fcb1, fcW2, fcb2, out);
}

// round 11
// speedup vs baseline: 1.6232x; 1.5019x over previous
#include <cuda_runtime.h>
#include <mma.h>
#include <math.h>

using namespace nvcuda;

// Problem constants (match reference setup_inputs)
#define NN 100000      // nodes
#define NE 1600000     // edges
#define NG 128         // graphs
#define INF 128
#define HF  128
#define OF  64
#define HID 10
#define NCLS 10

#define SCAN_NB ((NN + 1023) / 1024)   // 98 blocks for the node scan

// ---------------- scratch (device globals; allocation-free) ----------------
__device__ __align__(128) float g_Y1[(size_t)NN * 128]; // feats @ W1 (unscaled)
__device__ __align__(128) float g_M1[(size_t)NN * 128]; // aggregated sum sO[s]*Y1[s]
__device__ __align__(128) float g_Y2[(size_t)NN * 64];  // h1 @ W2 (unscaled)
__device__ __align__(128) float g_M2[(size_t)NN * 64];  // aggregated sum sO[s]*Y2[s]
__device__ int   g_degO[NN];
__device__ int   g_degI[NN];
__device__ float g_sO[NN];
__device__ float g_sI[NN];
__device__ int   g_rowoff[NN + 1];   // CSR row offsets (by dst)
__device__ int   g_cursor[NN];       // fill cursors
__device__ int   g_csrc[NE];         // CSR column indices = src per dst-sorted edge
__device__ int   g_incl[NN];         // in-block inclusive scan (temp)
__device__ int   g_bsum[128];        // per-block totals -> exclusive offsets
__device__ float g_pooled[NG * 64];

// ---------------- setup kernels ----------------
__global__ void zero_deg_kernel() {
    int i = blockIdx.x * 256 + threadIdx.x;
    if (i < NN) { g_degO[i] = 0; g_degI[i] = 0; }
}

__global__ void degree_kernel(const int* __restrict__ src, const int* __restrict__ dst) {
    int i = blockIdx.x * 256 + threadIdx.x;
    if (i < NE) {
        atomicAdd(&g_degO[src[i]], 1);
        atomicAdd(&g_degI[dst[i]], 1);
    }
}

// Phase 1: per-block inclusive scan of g_degI (1024 nodes/block) + block totals.
__global__ void __launch_bounds__(1024) scan_phase1() {
    int i = blockIdx.x * 1024 + threadIdx.x;
    int v = (i < NN) ? g_degI[i] : 0;
    __shared__ int ps[1024];
    ps[threadIdx.x] = v;
    __syncthreads();
#pragma unroll
    for (int off = 1; off < 1024; off <<= 1) {
        int t = (threadIdx.x >= off) ? ps[threadIdx.x - off] : 0;
        __syncthreads();
        ps[threadIdx.x] += t;
        __syncthreads();
    }
    if (i < NN) g_incl[i] = ps[threadIdx.x];
    if (threadIdx.x == 1023) g_bsum[blockIdx.x] = ps[1023];
}

// Phase 2: one tiny block scans the 98 block totals -> exclusive block offsets.
__global__ void __launch_bounds__(128) scan_phase2() {
    int t = threadIdx.x;
    int v = (t < SCAN_NB) ? g_bsum[t] : 0;
    __shared__ int ps[128];
    ps[t] = v;
    __syncthreads();
#pragma unroll
    for (int off = 1; off < 128; off <<= 1) {
        int u = (t >= off) ? ps[t - off] : 0;
        __syncthreads();
        ps[t] += u;
        __syncthreads();
    }
    if (t < SCAN_NB) g_bsum[t] = ps[t] - v;      // exclusive offset for block t
    if (t == 127) g_rowoff[NN] = ps[127];        // grand total (= NE)
}

// Phase 3: write rowoff/cursor + normalization scales (degrees are final here).
__global__ void __launch_bounds__(1024) scan_phase3() {
    int i = blockIdx.x * 1024 + threadIdx.x;
    if (i < NN) {
        int d = g_degI[i];
        int ex = g_bsum[blockIdx.x] + g_incl[i] - d;
        g_rowoff[i] = ex;
        g_cursor[i] = ex;
        g_sO[i] = rsqrtf(fmaxf((float)g_degO[i], 1.f));
        g_sI[i] = rsqrtf(fmaxf((float)d, 1.f));
    }
}

__global__ void fill_kernel(const int* __restrict__ src, const int* __restrict__ dst) {
    int e = blockIdx.x * 256 + threadIdx.x;
    if (e < NE) {
        int d = dst[e];
        int p = atomicAdd(&g_cursor[d], 1);
        g_csrc[p] = src[e];
    }
}

// ---------------- tf32 WMMA GEMMs ----------------
// Y1[100000 x 128] = feats[100000 x 128] @ W1[128 x 128]   (no scaling)
__global__ void __launch_bounds__(256) gemm1_kernel(const float* __restrict__ X,
                                                    const float* __restrict__ W) {
    __shared__ __align__(16) float As[128][36];
    __shared__ __align__(16) float Bs[32][132];
    const int tid = threadIdx.x;
    const int wid = tid >> 5;
    const int wm = wid & 3;        // 0..3  -> rows wm*32
    const int wn = wid >> 2;       // 0..1  -> cols wn*64
    const int row0 = blockIdx.x * 128;

    wmma::fragment<wmma::accumulator, 16, 16, 8, float> acc[2][4];
#pragma unroll
    for (int mi = 0; mi < 2; mi++)
#pragma unroll
        for (int nj = 0; nj < 4; nj++) wmma::fill_fragment(acc[mi][nj], 0.f);

    for (int k0 = 0; k0 < 128; k0 += 32) {
        // A tile: 128x32 floats = 1024 float4
#pragma unroll
        for (int i = 0; i < 4; i++) {
            int idx = tid + i * 256;
            int r = idx >> 3;
            int c4 = idx & 7;
            int g = row0 + r;
            float4 v = make_float4(0.f, 0.f, 0.f, 0.f);
            if (g < NN) v = *(const float4*)(X + (size_t)g * 128 + k0 + c4 * 4);
            *(float4*)&As[r][c4 * 4] = v;
        }
        // B tile: 32x128 floats
#pragma unroll
        for (int i = 0; i < 4; i++) {
            int idx = tid + i * 256;
            int r = idx >> 5;
            int c4 = idx & 31;
            *(float4*)&Bs[r][c4 * 4] = *(const float4*)(W + (size_t)(k0 + r) * 128 + c4 * 4);
        }
        __syncthreads();
#pragma unroll
        for (int kk = 0; kk < 32; kk += 8) {
            wmma::fragment<wmma::matrix_a, 16, 16, 8, wmma::precision::tf32, wmma::row_major> a0, a1;
            wmma::load_matrix_sync(a0, &As[wm * 32][kk], 36);
            wmma::load_matrix_sync(a1, &As[wm * 32 + 16][kk], 36);
#pragma unroll
            for (int e = 0; e < a0.num_elements; e++) {
                a0.x[e] = wmma::__float_to_tf32(a0.x[e]);
                a1.x[e] = wmma::__float_to_tf32(a1.x[e]);
            }
#pragma unroll
            for (int nj = 0; nj < 4; nj++) {
                wmma::fragment<wmma::matrix_b, 16, 16, 8, wmma::precision::tf32, wmma::row_major> b;
                wmma::load_matrix_sync(b, &Bs[kk][wn * 64 + nj * 16], 132);
#pragma unroll
                for (int e = 0; e < b.num_elements; e++) b.x[e] = wmma::__float_to_tf32(b.x[e]);
                wmma::mma_sync(acc[0][nj], a0, b, acc[0][nj]);
                wmma::mma_sync(acc[1][nj], a1, b, acc[1][nj]);
            }
        }
        __syncthreads();
    }
#pragma unroll
    for (int mi = 0; mi < 2; mi++) {
        int r = row0 + wm * 32 + mi * 16;
        if (r < NN) {
#pragma unroll
            for (int nj = 0; nj < 4; nj++)
                wmma::store_matrix_sync(g_Y1 + (size_t)r * 128 + wn * 64 + nj * 16,
                                        acc[mi][nj], 128, wmma::mem_row_major);
        }
    }
}

// Y2[100000 x 64] = relu(sI .* M1 + b1) @ W2[128 x 64]   (PRE fused into A load)
__global__ void __launch_bounds__(256) gemm2_kernel(const float* __restrict__ W,
                                                    const float* __restrict__ bias) {
    __shared__ __align__(16) float As[128][36];
    __shared__ __align__(16) float Bs[32][68];
    const int tid = threadIdx.x;
    const int wid = tid >> 5;
    const int wm = wid & 3;        // rows wm*32
    const int wn = wid >> 2;       // cols wn*32
    const int row0 = blockIdx.x * 128;

    wmma::fragment<wmma::accumulator, 16, 16, 8, float> acc[2][2];
#pragma unroll
    for (int mi = 0; mi < 2; mi++)
#pragma unroll
        for (int nj = 0; nj < 2; nj++) wmma::fill_fragment(acc[mi][nj], 0.f);

    for (int k0 = 0; k0 < 128; k0 += 32) {
#pragma unroll
        for (int i = 0; i < 4; i++) {
            int idx = tid + i * 256;
            int r = idx >> 3;
            int c4 = idx & 7;
            int g = row0 + r;
            float4 v = make_float4(0.f, 0.f, 0.f, 0.f);
            if (g < NN) {
                v = *(const float4*)(g_M1 + (size_t)g * 128 + k0 + c4 * 4);
                float si = g_sI[g];
                int kb = k0 + c4 * 4;
                v.x = fmaxf(fmaf(v.x, si, bias[kb + 0]), 0.f);
                v.y = fmaxf(fmaf(v.y, si, bias[kb + 1]), 0.f);
                v.z = fmaxf(fmaf(v.z, si, bias[kb + 2]), 0.f);
                v.w = fmaxf(fmaf(v.w, si, bias[kb + 3]), 0.f);
            }
            *(float4*)&As[r][c4 * 4] = v;
        }
        // B tile: 32x64 floats = 512 float4
#pragma unroll
        for (int i = 0; i < 2; i++) {
            int idx = tid + i * 256;
            int r = idx >> 4;
            int c4 = idx & 15;
            *(float4*)&Bs[r][c4 * 4] = *(const float4*)(W + (size_t)(k0 + r) * 64 + c4 * 4);
        }
        __syncthreads();
#pragma unroll
        for (int kk = 0; kk < 32; kk += 8) {
            wmma::fragment<wmma::matrix_a, 16, 16, 8, wmma::precision::tf32, wmma::row_major> a0, a1;
            wmma::load_matrix_sync(a0, &As[wm * 32][kk], 36);
            wmma::load_matrix_sync(a1, &As[wm * 32 + 16][kk], 36);
#pragma unroll
            for (int e = 0; e < a0.num_elements; e++) {
                a0.x[e] = wmma::__float_to_tf32(a0.x[e]);
                a1.x[e] = wmma::__float_to_tf32(a1.x[e]);
            }
#pragma unroll
            for (int nj = 0; nj < 2; nj++) {
                wmma::fragment<wmma::matrix_b, 16, 16, 8, wmma::precision::tf32, wmma::row_major> b;
                wmma::load_matrix_sync(b, &Bs[kk][wn * 32 + nj * 16], 68);
#pragma unroll
                for (int e = 0; e < b.num_elements; e++) b.x[e] = wmma::__float_to_tf32(b.x[e]);
                wmma::mma_sync(acc[0][nj], a0, b, acc[0][nj]);
                wmma::mma_sync(acc[1][nj], a1, b, acc[1][nj]);
            }
        }
        __syncthreads();
    }
#pragma unroll
    for (int mi = 0; mi < 2; mi++) {
        int r = row0 + wm * 32 + mi * 16;
        if (r < NN) {
#pragma unroll
            for (int nj = 0; nj < 2; nj++)
                wmma::store_matrix_sync(g_Y2 + (size_t)r * 64 + wn * 32 + nj * 16,
                                        acc[mi][nj], 64, wmma::mem_row_major);
        }
    }
}

// ---------------- CSR gather aggregation (no atomics) ----------------
// Layer 1: warp per node; lane = float4 column (32 x 16B = 128 floats).
// M1[n] = sum_{e in in(n)} sO[src_e] * Y1[src_e]
__global__ void __launch_bounds__(256) gather128_kernel() {
    int n = (blockIdx.x * 256 + threadIdx.x) >> 5;
    int lane = threadIdx.x & 31;
    if (n >= NN) return;
    int j = g_rowoff[n];
    int end = g_rowoff[n + 1];
    const float4* Y = (const float4*)g_Y1;
    float4 acc = make_float4(0.f, 0.f, 0.f, 0.f);
    for (; j + 3 < end; j += 4) {
        int s0 = g_csrc[j], s1 = g_csrc[j + 1], s2 = g_csrc[j + 2], s3 = g_csrc[j + 3];
        float c0 = g_sO[s0], c1 = g_sO[s1], c2 = g_sO[s2], c3 = g_sO[s3];
        float4 v0 = Y[(size_t)s0 * 32 + lane];
        float4 v1 = Y[(size_t)s1 * 32 + lane];
        float4 v2 = Y[(size_t)s2 * 32 + lane];
        float4 v3 = Y[(size_t)s3 * 32 + lane];
        acc.x += c0 * v0.x + c1 * v1.x + c2 * v2.x + c3 * v3.x;
        acc.y += c0 * v0.y + c1 * v1.y + c2 * v2.y + c3 * v3.y;
        acc.z += c0 * v0.z + c1 * v1.z + c2 * v2.z + c3 * v3.z;
        acc.w += c0 * v0.w + c1 * v1.w + c2 * v2.w + c3 * v3.w;
    }
    for (; j < end; j++) {
        int s = g_csrc[j];
        float c = g_sO[s];
        float4 v = Y[(size_t)s * 32 + lane];
        acc.x += c * v.x; acc.y += c * v.y; acc.z += c * v.z; acc.w += c * v.w;
    }
    ((float4*)g_M1)[(size_t)n * 32 + lane] = acc;
}

// Layer 2: half-warp per node; lane = float4 column (16 x 16B = 64 floats).
__global__ void __launch_bounds__(256) gather64_kernel() {
    int t = blockIdx.x * 256 + threadIdx.x;
    int n = t >> 4;
    int lane = t & 15;
    if (n >= NN) return;
    int j = g_rowoff[n];
    int end = g_rowoff[n + 1];
    const float4* Y = (const float4*)g_Y2;
    float4 acc = make_float4(0.f, 0.f, 0.f, 0.f);
    for (; j + 3 < end; j += 4) {
        int s0 = g_csrc[j], s1 = g_csrc[j + 1], s2 = g_csrc[j + 2], s3 = g_csrc[j + 3];
        float c0 = g_sO[s0], c1 = g_sO[s1], c2 = g_sO[s2], c3 = g_sO[s3];
        float4 v0 = Y[(size_t)s0 * 16 + lane];
        float4 v1 = Y[(size_t)s1 * 16 + lane];
        float4 v2 = Y[(size_t)s2 * 16 + lane];
        float4 v3 = Y[(size_t)s3 * 16 + lane];
        acc.x += c0 * v0.x + c1 * v1.x + c2 * v2.x + c3 * v3.x;
        acc.y += c0 * v0.y + c1 * v1.y + c2 * v2.y + c3 * v3.y;
        acc.z += c0 * v0.z + c1 * v1.z + c2 * v2.z + c3 * v3.z;
        acc.w += c0 * v0.w + c1 * v1.w + c2 * v2.w + c3 * v3.w;
    }
    for (; j < end; j++) {
        int s = g_csrc[j];
        float c = g_sO[s];
        float4 v = Y[(size_t)s * 16 + lane];
        acc.x += c * v.x; acc.y += c * v.y; acc.z += c * v.z; acc.w += c * v.w;
    }
    ((float4*)g_M2)[(size_t)n * 16 + lane] = acc;
}

// ---------------- pooling + head ----------------
__global__ void __launch_bounds__(256) pool_kernel(const int* __restrict__ gids,
                                                   const float* __restrict__ b2) {
    int g = blockIdx.x;
    int lo = 0, hi = NN;
    while (lo < hi) { int mid = (lo + hi) >> 1; if (gids[mid] < g) lo = mid + 1; else hi = mid; }
    int start = lo;
    hi = NN;
    while (lo < hi) { int mid = (lo + hi) >> 1; if (gids[mid] < g + 1) lo = mid + 1; else hi = mid; }
    int end = lo;

    int col = threadIdx.x & 63;
    int sub = threadIdx.x >> 6;   // 0..3
    float bc = b2[col];
    float acc = 0.f;
    for (int n = start + sub; n < end; n += 4) {
        float v = fmaf(g_M2[(size_t)n * 64 + col], g_sI[n], bc);
        acc += fmaxf(v, 0.f);
    }
    __shared__ float sacc[4][64];
    sacc[sub][col] = acc;
    __syncthreads();
    if (sub == 0) {
        float tot = sacc[0][col] + sacc[1][col] + sacc[2][col] + sacc[3][col];
        int cnt = end - start;
        float c = (float)(cnt > 0 ? cnt : 1);
        g_pooled[g * 64 + col] = tot / c;
    }
}

__global__ void __launch_bounds__(128) head_kernel(const float* __restrict__ fcW1,
                                                   const float* __restrict__ fcb1,
                                                   const float* __restrict__ fcW2,
                                                   const float* __restrict__ fcb2,
                                                   float* __restrict__ out) {
    __shared__ float w1s[OF * HID];
    __shared__ float w2s[HID * NCLS];
    for (int i = threadIdx.x; i < OF * HID; i += blockDim.x) w1s[i] = fcW1[i];
    for (int i = threadIdx.x; i < HID * NCLS; i += blockDim.x) w2s[i] = fcW2[i];
    __syncthreads();

    int g = threadIdx.x;
    if (g >= NG) return;
    float x[OF];
#pragma unroll
    for (int c = 0; c < OF; c++) x[c] = g_pooled[g * 64 + c];
    float z[HID];
#pragma unroll
    for (int h = 0; h < HID; h++) {
        float s = fcb1[h];
#pragma unroll
        for (int c = 0; c < OF; c++) s = fmaf(x[c], w1s[c * HID + h], s);
        z[h] = fmaxf(s, 0.f);
    }
    float o[NCLS];
    float mx = -1e30f;
#pragma unroll
    for (int k = 0; k < NCLS; k++) {
        float s = fcb2[k];
#pragma unroll
        for (int h = 0; h < HID; h++) s = fmaf(z[h], w2s[h * NCLS + k], s);
        o[k] = s;
        mx = fmaxf(mx, s);
    }
    float sum = 0.f;
#pragma unroll
    for (int k = 0; k < NCLS; k++) { o[k] = expf(o[k] - mx); sum += o[k]; }
    float inv = 1.f / sum;
#pragma unroll
    for (int k = 0; k < NCLS; k++) out[g * NCLS + k] = o[k] * inv;
}

// ---------------- launch ----------------
extern "C" void kernel_launch(void* const* d_in, const int* in_sizes, int n_in,
                              void* d_out, int out_size) {
    const float* feats = (const float*)d_in[0];
    const int*   src   = (const int*)d_in[1];
    const int*   dst   = (const int*)d_in[2];
    const int*   gids  = (const int*)d_in[3];
    const float* W1    = (const float*)d_in[4];
    const float* b1    = (const float*)d_in[5];
    const float* W2    = (const float*)d_in[6];
    const float* b2    = (const float*)d_in[7];
    const float* fcW1  = (const float*)d_in[8];
    const float* fcb1  = (const float*)d_in[9];
    const float* fcW2  = (const float*)d_in[10];
    const float* fcb2  = (const float*)d_in[11];
    float* out = (float*)d_out;

    // Degrees, CSR row offsets (parallel 3-phase scan), scales, CSR fill
    zero_deg_kernel<<<(NN + 255) / 256, 256>>>();
    degree_kernel<<<(NE + 255) / 256, 256>>>(src, dst);
    scan_phase1<<<SCAN_NB, 1024>>>();
    scan_phase2<<<1, 128>>>();
    scan_phase3<<<SCAN_NB, 1024>>>();
    fill_kernel<<<(NE + 255) / 256, 256>>>(src, dst);

    // Layer 1: Y1 = feats @ W1 (tf32);  M1[n] = sum sO[s] * Y1[s]
    gemm1_kernel<<<(NN + 127) / 128, 256>>>(feats, W1);
    gather128_kernel<<<(NN * 32 + 255) / 256, 256>>>();

    // Layer 2: A = relu(sI .* M1 + b1) fused; Y2 = A @ W2 (tf32); M2[n] = sum sO[s] * Y2[s]
    gemm2_kernel<<<(NN + 127) / 128, 256>>>(W2, b1);
    gather64_kernel<<<(NN * 16 + 255) / 256, 256>>>();

    // Pool (relu(sI .* M2 + b2), per-graph mean) + head MLP + softmax
    pool_kernel<<<NG, 256>>>(gids, b2);
    head_kernel<<<1, 128>>>(fcW1, fcb1, fcW2, fcb2, out);
}

// round 12
// speedup vs baseline: 1.8284x; 1.1264x over previous
#include <cuda_runtime.h>
#include <cuda_bf16.h>
#include <mma.h>
#include <math.h>

using namespace nvcuda;

// Problem constants (match reference setup_inputs)
#define NN 100000      // nodes
#define NE 1600000     // edges
#define NG 128         // graphs
#define INF 128
#define HF  128
#define OF  64
#define HID 10
#define NCLS 10

#define SCAN_NB ((NN + 1023) / 1024)   // 98 blocks for the node scan

// ---------------- scratch (device globals; allocation-free) ----------------
__device__ __align__(128) __nv_bfloat16 g_Y1h[(size_t)NN * 128]; // bf16(sO .* (feats@W1))
__device__ __align__(128) float g_M1[(size_t)NN * 128];          // edge-summed (fp32)
__device__ __align__(128) __nv_bfloat16 g_Y2h[(size_t)NN * 64];  // bf16(sO .* (h1@W2))
__device__ __align__(128) float g_M2[(size_t)NN * 64];           // edge-summed (fp32)
__device__ int   g_degO[NN];
__device__ int   g_degI[NN];
__device__ float g_sO[NN];
__device__ float g_sI[NN];
__device__ int   g_rowoff[NN + 1];   // CSR row offsets (by dst)
__device__ int   g_cursor[NN];       // fill cursors
__device__ int   g_csrc[NE];         // CSR column indices = src per dst-sorted edge
__device__ int   g_incl[NN];         // in-block inclusive scan (temp)
__device__ int   g_bsum[128];        // per-block totals -> exclusive offsets
__device__ float g_pooled[NG * 64];

// ---------------- setup kernels ----------------
__global__ void zero_deg_kernel() {
    int i = blockIdx.x * 256 + threadIdx.x;
    if (i < NN) { g_degO[i] = 0; g_degI[i] = 0; }
}

__global__ void degree_kernel(const int* __restrict__ src, const int* __restrict__ dst) {
    int i = blockIdx.x * 256 + threadIdx.x;
    if (i < NE) {
        atomicAdd(&g_degO[src[i]], 1);
        atomicAdd(&g_degI[dst[i]], 1);
    }
}

// Phase 1: per-block inclusive scan of g_degI (1024 nodes/block) + block totals.
__global__ void __launch_bounds__(1024) scan_phase1() {
    int i = blockIdx.x * 1024 + threadIdx.x;
    int v = (i < NN) ? g_degI[i] : 0;
    __shared__ int ps[1024];
    ps[threadIdx.x] = v;
    __syncthreads();
#pragma unroll
    for (int off = 1; off < 1024; off <<= 1) {
        int t = (threadIdx.x >= off) ? ps[threadIdx.x - off] : 0;
        __syncthreads();
        ps[threadIdx.x] += t;
        __syncthreads();
    }
    if (i < NN) g_incl[i] = ps[threadIdx.x];
    if (threadIdx.x == 1023) g_bsum[blockIdx.x] = ps[1023];
}

// Phase 2: one tiny block scans the 98 block totals -> exclusive block offsets.
__global__ void __launch_bounds__(128) scan_phase2() {
    int t = threadIdx.x;
    int v = (t < SCAN_NB) ? g_bsum[t] : 0;
    __shared__ int ps[128];
    ps[t] = v;
    __syncthreads();
#pragma unroll
    for (int off = 1; off < 128; off <<= 1) {
        int u = (t >= off) ? ps[t - off] : 0;
        __syncthreads();
        ps[t] += u;
        __syncthreads();
    }
    if (t < SCAN_NB) g_bsum[t] = ps[t] - v;      // exclusive offset for block t
    if (t == 127) g_rowoff[NN] = ps[127];        // grand total (= NE)
}

// Phase 3: write rowoff/cursor + normalization scales (degrees are final here).
__global__ void __launch_bounds__(1024) scan_phase3() {
    int i = blockIdx.x * 1024 + threadIdx.x;
    if (i < NN) {
        int d = g_degI[i];
        int ex = g_bsum[blockIdx.x] + g_incl[i] - d;
        g_rowoff[i] = ex;
        g_cursor[i] = ex;
        g_sO[i] = rsqrtf(fmaxf((float)g_degO[i], 1.f));
        g_sI[i] = rsqrtf(fmaxf((float)d, 1.f));
    }
}

__global__ void fill_kernel(const int* __restrict__ src, const int* __restrict__ dst) {
    int e = blockIdx.x * 256 + threadIdx.x;
    if (e < NE) {
        int d = dst[e];
        int p = atomicAdd(&g_cursor[d], 1);
        g_csrc[p] = src[e];
    }
}

// ---------------- tf32 WMMA GEMMs (bf16 epilogue, sO folded) ----------------
// Y1h[r] = bf16(sO[r] * (feats @ W1)[r])
__global__ void __launch_bounds__(256) gemm1_kernel(const float* __restrict__ X,
                                                    const float* __restrict__ W) {
    __shared__ __align__(16) float As[128][36];   // reused as epilogue staging
    __shared__ __align__(16) float Bs[32][132];
    const int tid = threadIdx.x;
    const int lane = tid & 31;
    const int wid = tid >> 5;
    const int wm = wid & 3;        // 0..3  -> rows wm*32
    const int wn = wid >> 2;       // 0..1  -> cols wn*64
    const int row0 = blockIdx.x * 128;

    wmma::fragment<wmma::accumulator, 16, 16, 8, float> acc[2][4];
#pragma unroll
    for (int mi = 0; mi < 2; mi++)
#pragma unroll
        for (int nj = 0; nj < 4; nj++) wmma::fill_fragment(acc[mi][nj], 0.f);

    for (int k0 = 0; k0 < 128; k0 += 32) {
        // A tile: 128x32 floats = 1024 float4
#pragma unroll
        for (int i = 0; i < 4; i++) {
            int idx = tid + i * 256;
            int r = idx >> 3;
            int c4 = idx & 7;
            int g = row0 + r;
            float4 v = make_float4(0.f, 0.f, 0.f, 0.f);
            if (g < NN) v = *(const float4*)(X + (size_t)g * 128 + k0 + c4 * 4);
            *(float4*)&As[r][c4 * 4] = v;
        }
        // B tile: 32x128 floats
#pragma unroll
        for (int i = 0; i < 4; i++) {
            int idx = tid + i * 256;
            int r = idx >> 5;
            int c4 = idx & 31;
            *(float4*)&Bs[r][c4 * 4] = *(const float4*)(W + (size_t)(k0 + r) * 128 + c4 * 4);
        }
        __syncthreads();
#pragma unroll
        for (int kk = 0; kk < 32; kk += 8) {
            wmma::fragment<wmma::matrix_a, 16, 16, 8, wmma::precision::tf32, wmma::row_major> a0, a1;
            wmma::load_matrix_sync(a0, &As[wm * 32][kk], 36);
            wmma::load_matrix_sync(a1, &As[wm * 32 + 16][kk], 36);
#pragma unroll
            for (int e = 0; e < a0.num_elements; e++) {
                a0.x[e] = wmma::__float_to_tf32(a0.x[e]);
                a1.x[e] = wmma::__float_to_tf32(a1.x[e]);
            }
#pragma unroll
            for (int nj = 0; nj < 4; nj++) {
                wmma::fragment<wmma::matrix_b, 16, 16, 8, wmma::precision::tf32, wmma::row_major> b;
                wmma::load_matrix_sync(b, &Bs[kk][wn * 64 + nj * 16], 132);
#pragma unroll
                for (int e = 0; e < b.num_elements; e++) b.x[e] = wmma::__float_to_tf32(b.x[e]);
                wmma::mma_sync(acc[0][nj], a0, b, acc[0][nj]);
                wmma::mma_sync(acc[1][nj], a1, b, acc[1][nj]);
            }
        }
        __syncthreads();
    }
    // ---- epilogue: stage fp32 tile in smem (As reused), scale by sO, store bf16 ----
    float* st = &As[0][0] + wid * 320;   // 16 rows x ld=20 per warp
    const int erow = lane >> 1;          // 2 lanes per row
    const int ecol = (lane & 1) * 8;     // 8 floats per lane
#pragma unroll
    for (int mi = 0; mi < 2; mi++) {
#pragma unroll
        for (int nj = 0; nj < 4; nj++) {
            wmma::store_matrix_sync(st, acc[mi][nj], 20, wmma::mem_row_major);
            __syncwarp();
            int r = row0 + wm * 32 + mi * 16 + erow;
            if (r < NN) {
                float so = g_sO[r];
                __nv_bfloat16 h[8];
#pragma unroll
                for (int q = 0; q < 8; q++)
                    h[q] = __float2bfloat16(st[erow * 20 + ecol + q] * so);
                *(uint4*)(g_Y1h + (size_t)r * 128 + wn * 64 + nj * 16 + ecol) = *(uint4*)h;
            }
            __syncwarp();
        }
    }
}

// Y2h[r] = bf16(sO[r] * (relu(sI .* M1 + b1) @ W2)[r])
__global__ void __launch_bounds__(256) gemm2_kernel(const float* __restrict__ W,
                                                    const float* __restrict__ bias) {
    __shared__ __align__(16) float As[128][36];
    __shared__ __align__(16) float Bs[32][68];
    const int tid = threadIdx.x;
    const int lane = tid & 31;
    const int wid = tid >> 5;
    const int wm = wid & 3;        // rows wm*32
    const int wn = wid >> 2;       // cols wn*32
    const int row0 = blockIdx.x * 128;

    wmma::fragment<wmma::accumulator, 16, 16, 8, float> acc[2][2];
#pragma unroll
    for (int mi = 0; mi < 2; mi++)
#pragma unroll
        for (int nj = 0; nj < 2; nj++) wmma::fill_fragment(acc[mi][nj], 0.f);

    for (int k0 = 0; k0 < 128; k0 += 32) {
#pragma unroll
        for (int i = 0; i < 4; i++) {
            int idx = tid + i * 256;
            int r = idx >> 3;
            int c4 = idx & 7;
            int g = row0 + r;
            float4 v = make_float4(0.f, 0.f, 0.f, 0.f);
            if (g < NN) {
                v = *(const float4*)(g_M1 + (size_t)g * 128 + k0 + c4 * 4);
                float si = g_sI[g];
                int kb = k0 + c4 * 4;
                v.x = fmaxf(fmaf(v.x, si, bias[kb + 0]), 0.f);
                v.y = fmaxf(fmaf(v.y, si, bias[kb + 1]), 0.f);
                v.z = fmaxf(fmaf(v.z, si, bias[kb + 2]), 0.f);
                v.w = fmaxf(fmaf(v.w, si, bias[kb + 3]), 0.f);
            }
            *(float4*)&As[r][c4 * 4] = v;
        }
        // B tile: 32x64 floats = 512 float4
#pragma unroll
        for (int i = 0; i < 2; i++) {
            int idx = tid + i * 256;
            int r = idx >> 4;
            int c4 = idx & 15;
            *(float4*)&Bs[r][c4 * 4] = *(const float4*)(W + (size_t)(k0 + r) * 64 + c4 * 4);
        }
        __syncthreads();
#pragma unroll
        for (int kk = 0; kk < 32; kk += 8) {
            wmma::fragment<wmma::matrix_a, 16, 16, 8, wmma::precision::tf32, wmma::row_major> a0, a1;
            wmma::load_matrix_sync(a0, &As[wm * 32][kk], 36);
            wmma::load_matrix_sync(a1, &As[wm * 32 + 16][kk], 36);
#pragma unroll
            for (int e = 0; e < a0.num_elements; e++) {
                a0.x[e] = wmma::__float_to_tf32(a0.x[e]);
                a1.x[e] = wmma::__float_to_tf32(a1.x[e]);
            }
#pragma unroll
            for (int nj = 0; nj < 2; nj++) {
                wmma::fragment<wmma::matrix_b, 16, 16, 8, wmma::precision::tf32, wmma::row_major> b;
                wmma::load_matrix_sync(b, &Bs[kk][wn * 32 + nj * 16], 68);
#pragma unroll
                for (int e = 0; e < b.num_elements; e++) b.x[e] = wmma::__float_to_tf32(b.x[e]);
                wmma::mma_sync(acc[0][nj], a0, b, acc[0][nj]);
                wmma::mma_sync(acc[1][nj], a1, b, acc[1][nj]);
            }
        }
        __syncthreads();
    }
    // ---- epilogue: scale by sO, store bf16 ----
    float* st = &As[0][0] + wid * 320;
    const int erow = lane >> 1;
    const int ecol = (lane & 1) * 8;
#pragma unroll
    for (int mi = 0; mi < 2; mi++) {
#pragma unroll
        for (int nj = 0; nj < 2; nj++) {
            wmma::store_matrix_sync(st, acc[mi][nj], 20, wmma::mem_row_major);
            __syncwarp();
            int r = row0 + wm * 32 + mi * 16 + erow;
            if (r < NN) {
                float so = g_sO[r];
                __nv_bfloat16 h[8];
#pragma unroll
                for (int q = 0; q < 8; q++)
                    h[q] = __float2bfloat16(st[erow * 20 + ecol + q] * so);
                *(uint4*)(g_Y2h + (size_t)r * 64 + wn * 32 + nj * 16 + ecol) = *(uint4*)h;
            }
            __syncwarp();
        }
    }
}

// ---------------- CSR gather aggregation (bf16 reads, fp32 accum) ----------------
// Layer 1: half-warp (16 lanes) per node; lane loads uint4 = 8 bf16 (256 B rows).
__global__ void __launch_bounds__(256) gather128_kernel() {
    int t = blockIdx.x * 256 + threadIdx.x;
    int n = t >> 4;
    int lane = t & 15;
    if (n >= NN) return;
    int j = g_rowoff[n];
    int end = g_rowoff[n + 1];
    const uint4* Y = (const uint4*)g_Y1h;   // row = 16 uint4
    float acc[8];
#pragma unroll
    for (int q = 0; q < 8; q++) acc[q] = 0.f;

    for (; j + 3 < end; j += 4) {
        int s0 = g_csrc[j], s1 = g_csrc[j + 1], s2 = g_csrc[j + 2], s3 = g_csrc[j + 3];
        uint4 v0 = Y[(size_t)s0 * 16 + lane];
        uint4 v1 = Y[(size_t)s1 * 16 + lane];
        uint4 v2 = Y[(size_t)s2 * 16 + lane];
        uint4 v3 = Y[(size_t)s3 * 16 + lane];
        const __nv_bfloat162* p0 = (const __nv_bfloat162*)&v0;
        const __nv_bfloat162* p1 = (const __nv_bfloat162*)&v1;
        const __nv_bfloat162* p2 = (const __nv_bfloat162*)&v2;
        const __nv_bfloat162* p3 = (const __nv_bfloat162*)&v3;
#pragma unroll
        for (int q = 0; q < 4; q++) {
            float2 f0 = __bfloat1622float2(p0[q]);
            float2 f1 = __bfloat1622float2(p1[q]);
            float2 f2 = __bfloat1622float2(p2[q]);
            float2 f3 = __bfloat1622float2(p3[q]);
            acc[2 * q + 0] += (f0.x + f1.x) + (f2.x + f3.x);
            acc[2 * q + 1] += (f0.y + f1.y) + (f2.y + f3.y);
        }
    }
    for (; j < end; j++) {
        int s = g_csrc[j];
        uint4 v = Y[(size_t)s * 16 + lane];
        const __nv_bfloat162* p = (const __nv_bfloat162*)&v;
#pragma unroll
        for (int q = 0; q < 4; q++) {
            float2 f = __bfloat1622float2(p[q]);
            acc[2 * q + 0] += f.x;
            acc[2 * q + 1] += f.y;
        }
    }
    float* o = g_M1 + (size_t)n * 128 + lane * 8;
    *(float4*)(o + 0) = make_float4(acc[0], acc[1], acc[2], acc[3]);
    *(float4*)(o + 4) = make_float4(acc[4], acc[5], acc[6], acc[7]);
}

// Layer 2: 8 lanes per node; lane loads uint4 = 8 bf16 (128 B rows).
__global__ void __launch_bounds__(256) gather64_kernel() {
    int t = blockIdx.x * 256 + threadIdx.x;
    int n = t >> 3;
    int lane = t & 7;
    if (n >= NN) return;
    int j = g_rowoff[n];
    int end = g_rowoff[n + 1];
    const uint4* Y = (const uint4*)g_Y2h;   // row = 8 uint4
    float acc[8];
#pragma unroll
    for (int q = 0; q < 8; q++) acc[q] = 0.f;

    for (; j + 3 < end; j += 4) {
        int s0 = g_csrc[j], s1 = g_csrc[j + 1], s2 = g_csrc[j + 2], s3 = g_csrc[j + 3];
        uint4 v0 = Y[(size_t)s0 * 8 + lane];
        uint4 v1 = Y[(size_t)s1 * 8 + lane];
        uint4 v2 = Y[(size_t)s2 * 8 + lane];
        uint4 v3 = Y[(size_t)s3 * 8 + lane];
        const __nv_bfloat162* p0 = (const __nv_bfloat162*)&v0;
        const __nv_bfloat162* p1 = (const __nv_bfloat162*)&v1;
        const __nv_bfloat162* p2 = (const __nv_bfloat162*)&v2;
        const __nv_bfloat162* p3 = (const __nv_bfloat162*)&v3;
#pragma unroll
        for (int q = 0; q < 4; q++) {
            float2 f0 = __bfloat1622float2(p0[q]);
            float2 f1 = __bfloat1622float2(p1[q]);
            float2 f2 = __bfloat1622float2(p2[q]);
            float2 f3 = __bfloat1622float2(p3[q]);
            acc[2 * q + 0] += (f0.x + f1.x) + (f2.x + f3.x);
            acc[2 * q + 1] += (f0.y + f1.y) + (f2.y + f3.y);
        }
    }
    for (; j < end; j++) {
        int s = g_csrc[j];
        uint4 v = Y[(size_t)s * 8 + lane];
        const __nv_bfloat162* p = (const __nv_bfloat162*)&v;
#pragma unroll
        for (int q = 0; q < 4; q++) {
            float2 f = __bfloat1622float2(p[q]);
            acc[2 * q + 0] += f.x;
            acc[2 * q + 1] += f.y;
        }
    }
    float* o = g_M2 + (size_t)n * 64 + lane * 8;
    *(float4*)(o + 0) = make_float4(acc[0], acc[1], acc[2], acc[3]);
    *(float4*)(o + 4) = make_float4(acc[4], acc[5], acc[6], acc[7]);
}

// ---------------- pooling + head ----------------
__global__ void __launch_bounds__(256) pool_kernel(const int* __restrict__ gids,
                                                   const float* __restrict__ b2) {
    int g = blockIdx.x;
    int lo = 0, hi = NN;
    while (lo < hi) { int mid = (lo + hi) >> 1; if (gids[mid] < g) lo = mid + 1; else hi = mid; }
    int start = lo;
    hi = NN;
    while (lo < hi) { int mid = (lo + hi) >> 1; if (gids[mid] < g + 1) lo = mid + 1; else hi = mid; }
    int end = lo;

    int col = threadIdx.x & 63;
    int sub = threadIdx.x >> 6;   // 0..3
    float bc = b2[col];
    float acc = 0.f;
    for (int n = start + sub; n < end; n += 4) {
        float v = fmaf(g_M2[(size_t)n * 64 + col], g_sI[n], bc);
        acc += fmaxf(v, 0.f);
    }
    __shared__ float sacc[4][64];
    sacc[sub][col] = acc;
    __syncthreads();
    if (sub == 0) {
        float tot = sacc[0][col] + sacc[1][col] + sacc[2][col] + sacc[3][col];
        int cnt = end - start;
        float c = (float)(cnt > 0 ? cnt : 1);
        g_pooled[g * 64 + col] = tot / c;
    }
}

__global__ void __launch_bounds__(128) head_kernel(const float* __restrict__ fcW1,
                                                   const float* __restrict__ fcb1,
                                                   const float* __restrict__ fcW2,
                                                   const float* __restrict__ fcb2,
                                                   float* __restrict__ out) {
    __shared__ float w1s[OF * HID];
    __shared__ float w2s[HID * NCLS];
    for (int i = threadIdx.x; i < OF * HID; i += blockDim.x) w1s[i] = fcW1[i];
    for (int i = threadIdx.x; i < HID * NCLS; i += blockDim.x) w2s[i] = fcW2[i];
    __syncthreads();

    int g = threadIdx.x;
    if (g >= NG) return;
    float x[OF];
#pragma unroll
    for (int c = 0; c < OF; c++) x[c] = g_pooled[g * 64 + c];
    float z[HID];
#pragma unroll
    for (int h = 0; h < HID; h++) {
        float s = fcb1[h];
#pragma unroll
        for (int c = 0; c < OF; c++) s = fmaf(x[c], w1s[c * HID + h], s);
        z[h] = fmaxf(s, 0.f);
    }
    float o[NCLS];
    float mx = -1e30f;
#pragma unroll
    for (int k = 0; k < NCLS; k++) {
        float s = fcb2[k];
#pragma unroll
        for (int h = 0; h < HID; h++) s = fmaf(z[h], w2s[h * NCLS + k], s);
        o[k] = s;
        mx = fmaxf(mx, s);
    }
    float sum = 0.f;
#pragma unroll
    for (int k = 0; k < NCLS; k++) { o[k] = expf(o[k] - mx); sum += o[k]; }
    float inv = 1.f / sum;
#pragma unroll
    for (int k = 0; k < NCLS; k++) out[g * NCLS + k] = o[k] * inv;
}

// ---------------- launch ----------------
extern "C" void kernel_launch(void* const* d_in, const int* in_sizes, int n_in,
                              void* d_out, int out_size) {
    const float* feats = (const float*)d_in[0];
    const int*   src   = (const int*)d_in[1];
    const int*   dst   = (const int*)d_in[2];
    const int*   gids  = (const int*)d_in[3];
    const float* W1    = (const float*)d_in[4];
    const float* b1    = (const float*)d_in[5];
    const float* W2    = (const float*)d_in[6];
    const float* b2    = (const float*)d_in[7];
    const float* fcW1  = (const float*)d_in[8];
    const float* fcb1  = (const float*)d_in[9];
    const float* fcW2  = (const float*)d_in[10];
    const float* fcb2  = (const float*)d_in[11];
    float* out = (float*)d_out;

    // Degrees, CSR row offsets (parallel 3-phase scan), scales, CSR fill
    zero_deg_kernel<<<(NN + 255) / 256, 256>>>();
    degree_kernel<<<(NE + 255) / 256, 256>>>(src, dst);
    scan_phase1<<<SCAN_NB, 1024>>>();
    scan_phase2<<<1, 128>>>();
    scan_phase3<<<SCAN_NB, 1024>>>();
    fill_kernel<<<(NE + 255) / 256, 256>>>(src, dst);

    // Layer 1: Y1h = bf16(sO .* (feats @ W1));  M1[n] = sum Y1h[src]
    gemm1_kernel<<<(NN + 127) / 128, 256>>>(feats, W1);
    gather128_kernel<<<(NN * 16 + 255) / 256, 256>>>();

    // Layer 2: A = relu(sI .* M1 + b1) fused; Y2h = bf16(sO .* (A @ W2)); M2[n] = sum Y2h[src]
    gemm2_kernel<<<(NN + 127) / 128, 256>>>(W2, b1);
    gather64_kernel<<<(NN * 8 + 255) / 256, 256>>>();

    // Pool (relu(sI .* M2 + b2), per-graph mean) + head MLP + softmax
    pool_kernel<<<NG, 256>>>(gids, b2);
    head_kernel<<<1, 128>>>(fcW1, fcb1, fcW2, fcb2, out);
}

// round 13
// speedup vs baseline: 1.8636x; 1.0193x over previous
#include <cuda_runtime.h>
#include <cuda_bf16.h>
#include <mma.h>
#include <math.h>

using namespace nvcuda;

// Problem constants (match reference setup_inputs)
#define NN 100000      // nodes
#define NE 1600000     // edges
#define NG 128         // graphs
#define INF 128
#define HF  128
#define OF  64
#define HID 10
#define NCLS 10

#define SCAN_NB ((NN + 1023) / 1024)   // 98 blocks for the node scan

// ---------------- scratch (device globals; allocation-free) ----------------
__device__ __align__(128) __nv_bfloat16 g_Y1h[(size_t)NN * 128]; // bf16(feats@W1), UNscaled
__device__ __align__(128) float g_M1[(size_t)NN * 128];          // sum sO[s]*Y1h[s] (fp32)
__device__ __align__(128) __nv_bfloat16 g_Y2h[(size_t)NN * 64];  // bf16(sO .* (h1@W2))
__device__ __align__(128) float g_M2[(size_t)NN * 64];           // edge-summed (fp32)
__device__ int   g_degO[NN];
__device__ int   g_degI[NN];
__device__ float g_sO[NN];
__device__ float g_sI[NN];
__device__ int   g_rowoff[NN + 1];   // CSR row offsets (by dst)
__device__ int   g_cursor[NN];       // fill cursors
__device__ int   g_csrc[NE];         // CSR column indices = src per dst-sorted edge
__device__ int   g_incl[NN];         // in-block inclusive scan (temp)
__device__ int   g_bsum[128];        // per-block totals -> exclusive offsets
__device__ float g_pooled[NG * 64];

// ---------------- setup kernels ----------------
__global__ void zero_deg_kernel() {
    int i = blockIdx.x * 256 + threadIdx.x;
    if (i < NN) { g_degO[i] = 0; g_degI[i] = 0; }
}

__global__ void degree_kernel(const int* __restrict__ src, const int* __restrict__ dst) {
    int i = blockIdx.x * 256 + threadIdx.x;
    if (i < NE) {
        atomicAdd(&g_degO[src[i]], 1);
        atomicAdd(&g_degI[dst[i]], 1);
    }
}

// Phase 1: per-block inclusive scan of g_degI (1024 nodes/block) + block totals.
__global__ void __launch_bounds__(1024) scan_phase1() {
    int i = blockIdx.x * 1024 + threadIdx.x;
    int v = (i < NN) ? g_degI[i] : 0;
    __shared__ int ps[1024];
    ps[threadIdx.x] = v;
    __syncthreads();
#pragma unroll
    for (int off = 1; off < 1024; off <<= 1) {
        int t = (threadIdx.x >= off) ? ps[threadIdx.x - off] : 0;
        __syncthreads();
        ps[threadIdx.x] += t;
        __syncthreads();
    }
    if (i < NN) g_incl[i] = ps[threadIdx.x];
    if (threadIdx.x == 1023) g_bsum[blockIdx.x] = ps[1023];
}

// Phase 2: one tiny block scans the 98 block totals -> exclusive block offsets.
__global__ void __launch_bounds__(128) scan_phase2() {
    int t = threadIdx.x;
    int v = (t < SCAN_NB) ? g_bsum[t] : 0;
    __shared__ int ps[128];
    ps[t] = v;
    __syncthreads();
#pragma unroll
    for (int off = 1; off < 128; off <<= 1) {
        int u = (t >= off) ? ps[t - off] : 0;
        __syncthreads();
        ps[t] += u;
        __syncthreads();
    }
    if (t < SCAN_NB) g_bsum[t] = ps[t] - v;      // exclusive offset for block t
    if (t == 127) g_rowoff[NN] = ps[127];        // grand total (= NE)
}

// Phase 3: write rowoff/cursor + normalization scales (degrees are final here).
__global__ void __launch_bounds__(1024) scan_phase3() {
    int i = blockIdx.x * 1024 + threadIdx.x;
    if (i < NN) {
        int d = g_degI[i];
        int ex = g_bsum[blockIdx.x] + g_incl[i] - d;
        g_rowoff[i] = ex;
        g_cursor[i] = ex;
        g_sO[i] = rsqrtf(fmaxf((float)g_degO[i], 1.f));
        g_sI[i] = rsqrtf(fmaxf((float)d, 1.f));
    }
}

__global__ void fill_kernel(const int* __restrict__ src, const int* __restrict__ dst) {
    int e = blockIdx.x * 256 + threadIdx.x;
    if (e < NE) {
        int d = dst[e];
        int p = atomicAdd(&g_cursor[d], 1);
        g_csrc[p] = src[e];
    }
}

// ---------------- tf32 WMMA GEMMs ----------------
// Y1h[r] = bf16((feats @ W1)[r])   -- UNscaled; sO applied in gather128.
// Independent of the CSR/degree chain -> runs on a side stream.
__global__ void __launch_bounds__(256) gemm1_kernel(const float* __restrict__ X,
                                                    const float* __restrict__ W) {
    __shared__ __align__(16) float As[128][36];   // reused as epilogue staging
    __shared__ __align__(16) float Bs[32][132];
    const int tid = threadIdx.x;
    const int lane = tid & 31;
    const int wid = tid >> 5;
    const int wm = wid & 3;        // 0..3  -> rows wm*32
    const int wn = wid >> 2;       // 0..1  -> cols wn*64
    const int row0 = blockIdx.x * 128;

    wmma::fragment<wmma::accumulator, 16, 16, 8, float> acc[2][4];
#pragma unroll
    for (int mi = 0; mi < 2; mi++)
#pragma unroll
        for (int nj = 0; nj < 4; nj++) wmma::fill_fragment(acc[mi][nj], 0.f);

    for (int k0 = 0; k0 < 128; k0 += 32) {
        // A tile: 128x32 floats = 1024 float4
#pragma unroll
        for (int i = 0; i < 4; i++) {
            int idx = tid + i * 256;
            int r = idx >> 3;
            int c4 = idx & 7;
            int g = row0 + r;
            float4 v = make_float4(0.f, 0.f, 0.f, 0.f);
            if (g < NN) v = *(const float4*)(X + (size_t)g * 128 + k0 + c4 * 4);
            *(float4*)&As[r][c4 * 4] = v;
        }
        // B tile: 32x128 floats
#pragma unroll
        for (int i = 0; i < 4; i++) {
            int idx = tid + i * 256;
            int r = idx >> 5;
            int c4 = idx & 31;
            *(float4*)&Bs[r][c4 * 4] = *(const float4*)(W + (size_t)(k0 + r) * 128 + c4 * 4);
        }
        __syncthreads();
#pragma unroll
        for (int kk = 0; kk < 32; kk += 8) {
            wmma::fragment<wmma::matrix_a, 16, 16, 8, wmma::precision::tf32, wmma::row_major> a0, a1;
            wmma::load_matrix_sync(a0, &As[wm * 32][kk], 36);
            wmma::load_matrix_sync(a1, &As[wm * 32 + 16][kk], 36);
#pragma unroll
            for (int e = 0; e < a0.num_elements; e++) {
                a0.x[e] = wmma::__float_to_tf32(a0.x[e]);
                a1.x[e] = wmma::__float_to_tf32(a1.x[e]);
            }
#pragma unroll
            for (int nj = 0; nj < 4; nj++) {
                wmma::fragment<wmma::matrix_b, 16, 16, 8, wmma::precision::tf32, wmma::row_major> b;
                wmma::load_matrix_sync(b, &Bs[kk][wn * 64 + nj * 16], 132);
#pragma unroll
                for (int e = 0; e < b.num_elements; e++) b.x[e] = wmma::__float_to_tf32(b.x[e]);
                wmma::mma_sync(acc[0][nj], a0, b, acc[0][nj]);
                wmma::mma_sync(acc[1][nj], a1, b, acc[1][nj]);
            }
        }
        __syncthreads();
    }
    // ---- epilogue: stage fp32 tile in smem (As reused), store bf16 (no scaling) ----
    float* st = &As[0][0] + wid * 320;   // 16 rows x ld=20 per warp
    const int erow = lane >> 1;          // 2 lanes per row
    const int ecol = (lane & 1) * 8;     // 8 floats per lane
#pragma unroll
    for (int mi = 0; mi < 2; mi++) {
#pragma unroll
        for (int nj = 0; nj < 4; nj++) {
            wmma::store_matrix_sync(st, acc[mi][nj], 20, wmma::mem_row_major);
            __syncwarp();
            int r = row0 + wm * 32 + mi * 16 + erow;
            if (r < NN) {
                __nv_bfloat16 h[8];
#pragma unroll
                for (int q = 0; q < 8; q++)
                    h[q] = __float2bfloat16(st[erow * 20 + ecol + q]);
                *(uint4*)(g_Y1h + (size_t)r * 128 + wn * 64 + nj * 16 + ecol) = *(uint4*)h;
            }
            __syncwarp();
        }
    }
}

// Y2h[r] = bf16(sO[r] * (relu(sI .* M1 + b1) @ W2)[r])
__global__ void __launch_bounds__(256) gemm2_kernel(const float* __restrict__ W,
                                                    const float* __restrict__ bias) {
    __shared__ __align__(16) float As[128][36];
    __shared__ __align__(16) float Bs[32][68];
    const int tid = threadIdx.x;
    const int lane = tid & 31;
    const int wid = tid >> 5;
    const int wm = wid & 3;        // rows wm*32
    const int wn = wid >> 2;       // cols wn*32
    const int row0 = blockIdx.x * 128;

    wmma::fragment<wmma::accumulator, 16, 16, 8, float> acc[2][2];
#pragma unroll
    for (int mi = 0; mi < 2; mi++)
#pragma unroll
        for (int nj = 0; nj < 2; nj++) wmma::fill_fragment(acc[mi][nj], 0.f);

    for (int k0 = 0; k0 < 128; k0 += 32) {
#pragma unroll
        for (int i = 0; i < 4; i++) {
            int idx = tid + i * 256;
            int r = idx >> 3;
            int c4 = idx & 7;
            int g = row0 + r;
            float4 v = make_float4(0.f, 0.f, 0.f, 0.f);
            if (g < NN) {
                v = *(const float4*)(g_M1 + (size_t)g * 128 + k0 + c4 * 4);
                float si = g_sI[g];
                int kb = k0 + c4 * 4;
                v.x = fmaxf(fmaf(v.x, si, bias[kb + 0]), 0.f);
                v.y = fmaxf(fmaf(v.y, si, bias[kb + 1]), 0.f);
                v.z = fmaxf(fmaf(v.z, si, bias[kb + 2]), 0.f);
                v.w = fmaxf(fmaf(v.w, si, bias[kb + 3]), 0.f);
            }
            *(float4*)&As[r][c4 * 4] = v;
        }
        // B tile: 32x64 floats = 512 float4
#pragma unroll
        for (int i = 0; i < 2; i++) {
            int idx = tid + i * 256;
            int r = idx >> 4;
            int c4 = idx & 15;
            *(float4*)&Bs[r][c4 * 4] = *(const float4*)(W + (size_t)(k0 + r) * 64 + c4 * 4);
        }
        __syncthreads();
#pragma unroll
        for (int kk = 0; kk < 32; kk += 8) {
            wmma::fragment<wmma::matrix_a, 16, 16, 8, wmma::precision::tf32, wmma::row_major> a0, a1;
            wmma::load_matrix_sync(a0, &As[wm * 32][kk], 36);
            wmma::load_matrix_sync(a1, &As[wm * 32 + 16][kk], 36);
#pragma unroll
            for (int e = 0; e < a0.num_elements; e++) {
                a0.x[e] = wmma::__float_to_tf32(a0.x[e]);
                a1.x[e] = wmma::__float_to_tf32(a1.x[e]);
            }
#pragma unroll
            for (int nj = 0; nj < 2; nj++) {
                wmma::fragment<wmma::matrix_b, 16, 16, 8, wmma::precision::tf32, wmma::row_major> b;
                wmma::load_matrix_sync(b, &Bs[kk][wn * 32 + nj * 16], 68);
#pragma unroll
                for (int e = 0; e < b.num_elements; e++) b.x[e] = wmma::__float_to_tf32(b.x[e]);
                wmma::mma_sync(acc[0][nj], a0, b, acc[0][nj]);
                wmma::mma_sync(acc[1][nj], a1, b, acc[1][nj]);
            }
        }
        __syncthreads();
    }
    // ---- epilogue: scale by sO, store bf16 ----
    float* st = &As[0][0] + wid * 320;
    const int erow = lane >> 1;
    const int ecol = (lane & 1) * 8;
#pragma unroll
    for (int mi = 0; mi < 2; mi++) {
#pragma unroll
        for (int nj = 0; nj < 2; nj++) {
            wmma::store_matrix_sync(st, acc[mi][nj], 20, wmma::mem_row_major);
            __syncwarp();
            int r = row0 + wm * 32 + mi * 16 + erow;
            if (r < NN) {
                float so = g_sO[r];
                __nv_bfloat16 h[8];
#pragma unroll
                for (int q = 0; q < 8; q++)
                    h[q] = __float2bfloat16(st[erow * 20 + ecol + q] * so);
                *(uint4*)(g_Y2h + (size_t)r * 64 + wn * 32 + nj * 16 + ecol) = *(uint4*)h;
            }
            __syncwarp();
        }
    }
}

// ---------------- CSR gather aggregation (bf16 reads, fp32 accum) ----------------
// Layer 1: half-warp (16 lanes) per node; applies sO[src] per edge.
__global__ void __launch_bounds__(256) gather128_kernel() {
    int t = blockIdx.x * 256 + threadIdx.x;
    int n = t >> 4;
    int lane = t & 15;
    if (n >= NN) return;
    int j = g_rowoff[n];
    int end = g_rowoff[n + 1];
    const uint4* Y = (const uint4*)g_Y1h;   // row = 16 uint4
    float acc[8];
#pragma unroll
    for (int q = 0; q < 8; q++) acc[q] = 0.f;

    for (; j + 3 < end; j += 4) {
        int s0 = g_csrc[j], s1 = g_csrc[j + 1], s2 = g_csrc[j + 2], s3 = g_csrc[j + 3];
        float c0 = g_sO[s0], c1 = g_sO[s1], c2 = g_sO[s2], c3 = g_sO[s3];
        uint4 v0 = Y[(size_t)s0 * 16 + lane];
        uint4 v1 = Y[(size_t)s1 * 16 + lane];
        uint4 v2 = Y[(size_t)s2 * 16 + lane];
        uint4 v3 = Y[(size_t)s3 * 16 + lane];
        const __nv_bfloat162* p0 = (const __nv_bfloat162*)&v0;
        const __nv_bfloat162* p1 = (const __nv_bfloat162*)&v1;
        const __nv_bfloat162* p2 = (const __nv_bfloat162*)&v2;
        const __nv_bfloat162* p3 = (const __nv_bfloat162*)&v3;
#pragma unroll
        for (int q = 0; q < 4; q++) {
            float2 f0 = __bfloat1622float2(p0[q]);
            float2 f1 = __bfloat1622float2(p1[q]);
            float2 f2 = __bfloat1622float2(p2[q]);
            float2 f3 = __bfloat1622float2(p3[q]);
            acc[2 * q + 0] += c0 * f0.x + c1 * f1.x + c2 * f2.x + c3 * f3.x;
            acc[2 * q + 1] += c0 * f0.y + c1 * f1.y + c2 * f2.y + c3 * f3.y;
        }
    }
    for (; j < end; j++) {
        int s = g_csrc[j];
        float c = g_sO[s];
        uint4 v = Y[(size_t)s * 16 + lane];
        const __nv_bfloat162* p = (const __nv_bfloat162*)&v;
#pragma unroll
        for (int q = 0; q < 4; q++) {
            float2 f = __bfloat1622float2(p[q]);
            acc[2 * q + 0] += c * f.x;
            acc[2 * q + 1] += c * f.y;
        }
    }
    float* o = g_M1 + (size_t)n * 128 + lane * 8;
    *(float4*)(o + 0) = make_float4(acc[0], acc[1], acc[2], acc[3]);
    *(float4*)(o + 4) = make_float4(acc[4], acc[5], acc[6], acc[7]);
}

// Layer 2: 8 lanes per node; lane loads uint4 = 8 bf16 (128 B rows). sO pre-folded.
__global__ void __launch_bounds__(256) gather64_kernel() {
    int t = blockIdx.x * 256 + threadIdx.x;
    int n = t >> 3;
    int lane = t & 7;
    if (n >= NN) return;
    int j = g_rowoff[n];
    int end = g_rowoff[n + 1];
    const uint4* Y = (const uint4*)g_Y2h;   // row = 8 uint4
    float acc[8];
#pragma unroll
    for (int q = 0; q < 8; q++) acc[q] = 0.f;

    for (; j + 3 < end; j += 4) {
        int s0 = g_csrc[j], s1 = g_csrc[j + 1], s2 = g_csrc[j + 2], s3 = g_csrc[j + 3];
        uint4 v0 = Y[(size_t)s0 * 8 + lane];
        uint4 v1 = Y[(size_t)s1 * 8 + lane];
        uint4 v2 = Y[(size_t)s2 * 8 + lane];
        uint4 v3 = Y[(size_t)s3 * 8 + lane];
        const __nv_bfloat162* p0 = (const __nv_bfloat162*)&v0;
        const __nv_bfloat162* p1 = (const __nv_bfloat162*)&v1;
        const __nv_bfloat162* p2 = (const __nv_bfloat162*)&v2;
        const __nv_bfloat162* p3 = (const __nv_bfloat162*)&v3;
#pragma unroll
        for (int q = 0; q < 4; q++) {
            float2 f0 = __bfloat1622float2(p0[q]);
            float2 f1 = __bfloat1622float2(p1[q]);
            float2 f2 = __bfloat1622float2(p2[q]);
            float2 f3 = __bfloat1622float2(p3[q]);
            acc[2 * q + 0] += (f0.x + f1.x) + (f2.x + f3.x);
            acc[2 * q + 1] += (f0.y + f1.y) + (f2.y + f3.y);
        }
    }
    for (; j < end; j++) {
        int s = g_csrc[j];
        uint4 v = Y[(size_t)s * 8 + lane];
        const __nv_bfloat162* p = (const __nv_bfloat162*)&v;
#pragma unroll
        for (int q = 0; q < 4; q++) {
            float2 f = __bfloat1622float2(p[q]);
            acc[2 * q + 0] += f.x;
            acc[2 * q + 1] += f.y;
        }
    }
    float* o = g_M2 + (size_t)n * 64 + lane * 8;
    *(float4*)(o + 0) = make_float4(acc[0], acc[1], acc[2], acc[3]);
    *(float4*)(o + 4) = make_float4(acc[4], acc[5], acc[6], acc[7]);
}

// ---------------- pooling + head ----------------
__global__ void __launch_bounds__(256) pool_kernel(const int* __restrict__ gids,
                                                   const float* __restrict__ b2) {
    int g = blockIdx.x;
    int lo = 0, hi = NN;
    while (lo < hi) { int mid = (lo + hi) >> 1; if (gids[mid] < g) lo = mid + 1; else hi = mid; }
    int start = lo;
    hi = NN;
    while (lo < hi) { int mid = (lo + hi) >> 1; if (gids[mid] < g + 1) lo = mid + 1; else hi = mid; }
    int end = lo;

    int col = threadIdx.x & 63;
    int sub = threadIdx.x >> 6;   // 0..3
    float bc = b2[col];
    float acc = 0.f;
    for (int n = start + sub; n < end; n += 4) {
        float v = fmaf(g_M2[(size_t)n * 64 + col], g_sI[n], bc);
        acc += fmaxf(v, 0.f);
    }
    __shared__ float sacc[4][64];
    sacc[sub][col] = acc;
    __syncthreads();
    if (sub == 0) {
        float tot = sacc[0][col] + sacc[1][col] + sacc[2][col] + sacc[3][col];
        int cnt = end - start;
        float c = (float)(cnt > 0 ? cnt : 1);
        g_pooled[g * 64 + col] = tot / c;
    }
}

__global__ void __launch_bounds__(128) head_kernel(const float* __restrict__ fcW1,
                                                   const float* __restrict__ fcb1,
                                                   const float* __restrict__ fcW2,
                                                   const float* __restrict__ fcb2,
                                                   float* __restrict__ out) {
    __shared__ float w1s[OF * HID];
    __shared__ float w2s[HID * NCLS];
    for (int i = threadIdx.x; i < OF * HID; i += blockDim.x) w1s[i] = fcW1[i];
    for (int i = threadIdx.x; i < HID * NCLS; i += blockDim.x) w2s[i] = fcW2[i];
    __syncthreads();

    int g = threadIdx.x;
    if (g >= NG) return;
    float x[OF];
#pragma unroll
    for (int c = 0; c < OF; c++) x[c] = g_pooled[g * 64 + c];
    float z[HID];
#pragma unroll
    for (int h = 0; h < HID; h++) {
        float s = fcb1[h];
#pragma unroll
        for (int c = 0; c < OF; c++) s = fmaf(x[c], w1s[c * HID + h], s);
        z[h] = fmaxf(s, 0.f);
    }
    float o[NCLS];
    float mx = -1e30f;
#pragma unroll
    for (int k = 0; k < NCLS; k++) {
        float s = fcb2[k];
#pragma unroll
        for (int h = 0; h < HID; h++) s = fmaf(z[h], w2s[h * NCLS + k], s);
        o[k] = s;
        mx = fmaxf(mx, s);
    }
    float sum = 0.f;
#pragma unroll
    for (int k = 0; k < NCLS; k++) { o[k] = expf(o[k] - mx); sum += o[k]; }
    float inv = 1.f / sum;
#pragma unroll
    for (int k = 0; k < NCLS; k++) out[g * NCLS + k] = o[k] * inv;
}

// ---------------- launch ----------------
extern "C" void kernel_launch(void* const* d_in, const int* in_sizes, int n_in,
                              void* d_out, int out_size) {
    const float* feats = (const float*)d_in[0];
    const int*   src   = (const int*)d_in[1];
    const int*   dst   = (const int*)d_in[2];
    const int*   gids  = (const int*)d_in[3];
    const float* W1    = (const float*)d_in[4];
    const float* b1    = (const float*)d_in[5];
    const float* W2    = (const float*)d_in[6];
    const float* b2    = (const float*)d_in[7];
    const float* fcW1  = (const float*)d_in[8];
    const float* fcb1  = (const float*)d_in[9];
    const float* fcW2  = (const float*)d_in[10];
    const float* fcb2  = (const float*)d_in[11];
    float* out = (float*)d_out;

    // Side stream + fork/join events, created once on the (non-capturing)
    // correctness call; reused during graph capture. Identical launches every call.
    static cudaStream_t s2 = nullptr;
    static cudaEvent_t evFork = nullptr, evJoin = nullptr;
    if (s2 == nullptr) {
        cudaStreamCreateWithFlags(&s2, cudaStreamNonBlocking);
        cudaEventCreateWithFlags(&evFork, cudaEventDisableTiming);
        cudaEventCreateWithFlags(&evJoin, cudaEventDisableTiming);
    }

    // Fork: gemm1 (feats@W1 -> bf16, unscaled) is independent of the CSR build.
    cudaEventRecord(evFork, 0);
    cudaStreamWaitEvent(s2, evFork, 0);
    gemm1_kernel<<<(NN + 127) / 128, 256, 0, s2>>>(feats, W1);
    cudaEventRecord(evJoin, s2);

    // Main stream: degrees, CSR row offsets (3-phase scan), scales, CSR fill
    zero_deg_kernel<<<(NN + 255) / 256, 256>>>();
    degree_kernel<<<(NE + 255) / 256, 256>>>(src, dst);
    scan_phase1<<<SCAN_NB, 1024>>>();
    scan_phase2<<<1, 128>>>();
    scan_phase3<<<SCAN_NB, 1024>>>();
    fill_kernel<<<(NE + 255) / 256, 256>>>(src, dst);

    // Join: gather needs both Y1h (s2) and the CSR (main stream).
    cudaStreamWaitEvent(0, evJoin, 0);

    // Layer 1 aggregation: M1[n] = sum sO[s] * Y1h[s]
    gather128_kernel<<<(NN * 16 + 255) / 256, 256>>>();

    // Layer 2: A = relu(sI .* M1 + b1) fused; Y2h = bf16(sO .* (A @ W2)); M2[n] = sum Y2h[src]
    gemm2_kernel<<<(NN + 127) / 128, 256>>>(W2, b1);
    gather64_kernel<<<(NN * 8 + 255) / 256, 256>>>();

    // Pool (relu(sI .* M2 + b2), per-graph mean) + head MLP + softmax
    pool_kernel<<<NG, 256>>>(gids, b2);
    head_kernel<<<1, 128>>>(fcW1, fcb1, fcW2, fcb2, out);
}

// round 14
// speedup vs baseline: 1.9368x; 1.0393x over previous
#include <cuda_runtime.h>
#include <cuda_bf16.h>
#include <mma.h>
#include <math.h>

using namespace nvcuda;

// Problem constants (match reference setup_inputs)
#define NN 100000      // nodes
#define NE 1600000     // edges
#define NG 128         // graphs
#define INF 128
#define HF  128
#define OF  64
#define HID 10
#define NCLS 10

#define SCAN_NB ((NN + 1023) / 1024)   // 98 blocks for the node scan

// ---------------- scratch (device globals; allocation-free) ----------------
__device__ __align__(128) __nv_bfloat16 g_Y1h[(size_t)NN * 128]; // bf16(feats@W1), UNscaled
__device__ __align__(128) __nv_bfloat16 g_A1h[(size_t)NN * 128]; // bf16(relu(sI.*M1+b1)) = h1
__device__ __align__(128) __nv_bfloat16 g_Y2h[(size_t)NN * 64];  // bf16(sO .* (h1@W2))
__device__ int   g_degO[NN];
__device__ int   g_degI[NN];
__device__ float g_sO[NN];
__device__ float g_sI[NN];
__device__ int   g_rowoff[NN + 1];   // CSR row offsets (by dst)
__device__ int   g_cursor[NN];       // fill cursors
__device__ int   g_csrc[NE];         // CSR column indices = src per dst-sorted edge
__device__ int   g_incl[NN];         // in-block inclusive scan (temp)
__device__ int   g_bsum[128];        // per-block totals
__device__ float g_pooled[NG * 64];  // per-graph sums (atomics)

// ---------------- setup kernels ----------------
__global__ void zero_deg_kernel() {
    int i = blockIdx.x * 256 + threadIdx.x;
    if (i < NN) { g_degO[i] = 0; g_degI[i] = 0; }
    if (i < NG * 64) g_pooled[i] = 0.f;
}

__global__ void degree_kernel(const int* __restrict__ src, const int* __restrict__ dst) {
    int i = blockIdx.x * 256 + threadIdx.x;
    if (i < NE) {
        atomicAdd(&g_degO[src[i]], 1);
        atomicAdd(&g_degI[dst[i]], 1);
    }
}

// Phase 1: per-block inclusive scan of g_degI (1024 nodes/block) + block totals.
__global__ void __launch_bounds__(1024) scan_phase1() {
    int i = blockIdx.x * 1024 + threadIdx.x;
    int v = (i < NN) ? g_degI[i] : 0;
    __shared__ int ps[1024];
    ps[threadIdx.x] = v;
    __syncthreads();
#pragma unroll
    for (int off = 1; off < 1024; off <<= 1) {
        int t = (threadIdx.x >= off) ? ps[threadIdx.x - off] : 0;
        __syncthreads();
        ps[threadIdx.x] += t;
        __syncthreads();
    }
    if (i < NN) g_incl[i] = ps[threadIdx.x];
    if (threadIdx.x == 1023) g_bsum[blockIdx.x] = ps[1023];
}

// Phase 3 (merged w/ phase2): every block redundantly scans the 98 block totals
// in smem, then writes rowoff/cursor + normalization scales.
__global__ void __launch_bounds__(1024) scan_phase3() {
    __shared__ int bs[128];
    if (threadIdx.x < 128) bs[threadIdx.x] = (threadIdx.x < SCAN_NB) ? g_bsum[threadIdx.x] : 0;
    __syncthreads();
#pragma unroll
    for (int off = 1; off < 128; off <<= 1) {
        int u = 0;
        if (threadIdx.x < 128 && threadIdx.x >= off) u = bs[threadIdx.x - off];
        __syncthreads();
        if (threadIdx.x < 128) bs[threadIdx.x] += u;
        __syncthreads();
    }
    int exoff = (blockIdx.x == 0) ? 0 : bs[blockIdx.x - 1];
    if (blockIdx.x == 0 && threadIdx.x == 0) g_rowoff[NN] = bs[SCAN_NB - 1];

    int i = blockIdx.x * 1024 + threadIdx.x;
    if (i < NN) {
        int d = g_degI[i];
        int ex = exoff + g_incl[i] - d;
        g_rowoff[i] = ex;
        g_cursor[i] = ex;
        g_sO[i] = rsqrtf(fmaxf((float)g_degO[i], 1.f));
        g_sI[i] = rsqrtf(fmaxf((float)d, 1.f));
    }
}

__global__ void fill_kernel(const int* __restrict__ src, const int* __restrict__ dst) {
    int e = blockIdx.x * 256 + threadIdx.x;
    if (e < NE) {
        int d = dst[e];
        int p = atomicAdd(&g_cursor[d], 1);
        g_csrc[p] = src[e];
    }
}

// ---------------- tf32 WMMA GEMMs ----------------
// Y1h[r] = bf16((feats @ W1)[r])   -- UNscaled; sO applied in gather128.
// Independent of the CSR/degree chain -> runs on a side stream.
__global__ void __launch_bounds__(256) gemm1_kernel(const float* __restrict__ X,
                                                    const float* __restrict__ W) {
    __shared__ __align__(16) float As[128][36];   // reused as epilogue staging
    __shared__ __align__(16) float Bs[32][132];
    const int tid = threadIdx.x;
    const int lane = tid & 31;
    const int wid = tid >> 5;
    const int wm = wid & 3;        // 0..3  -> rows wm*32
    const int wn = wid >> 2;       // 0..1  -> cols wn*64
    const int row0 = blockIdx.x * 128;

    wmma::fragment<wmma::accumulator, 16, 16, 8, float> acc[2][4];
#pragma unroll
    for (int mi = 0; mi < 2; mi++)
#pragma unroll
        for (int nj = 0; nj < 4; nj++) wmma::fill_fragment(acc[mi][nj], 0.f);

    for (int k0 = 0; k0 < 128; k0 += 32) {
        // A tile: 128x32 floats = 1024 float4
#pragma unroll
        for (int i = 0; i < 4; i++) {
            int idx = tid + i * 256;
            int r = idx >> 3;
            int c4 = idx & 7;
            int g = row0 + r;
            float4 v = make_float4(0.f, 0.f, 0.f, 0.f);
            if (g < NN) v = *(const float4*)(X + (size_t)g * 128 + k0 + c4 * 4);
            *(float4*)&As[r][c4 * 4] = v;
        }
        // B tile: 32x128 floats
#pragma unroll
        for (int i = 0; i < 4; i++) {
            int idx = tid + i * 256;
            int r = idx >> 5;
            int c4 = idx & 31;
            *(float4*)&Bs[r][c4 * 4] = *(const float4*)(W + (size_t)(k0 + r) * 128 + c4 * 4);
        }
        __syncthreads();
#pragma unroll
        for (int kk = 0; kk < 32; kk += 8) {
            wmma::fragment<wmma::matrix_a, 16, 16, 8, wmma::precision::tf32, wmma::row_major> a0, a1;
            wmma::load_matrix_sync(a0, &As[wm * 32][kk], 36);
            wmma::load_matrix_sync(a1, &As[wm * 32 + 16][kk], 36);
#pragma unroll
            for (int e = 0; e < a0.num_elements; e++) {
                a0.x[e] = wmma::__float_to_tf32(a0.x[e]);
                a1.x[e] = wmma::__float_to_tf32(a1.x[e]);
            }
#pragma unroll
            for (int nj = 0; nj < 4; nj++) {
                wmma::fragment<wmma::matrix_b, 16, 16, 8, wmma::precision::tf32, wmma::row_major> b;
                wmma::load_matrix_sync(b, &Bs[kk][wn * 64 + nj * 16], 132);
#pragma unroll
                for (int e = 0; e < b.num_elements; e++) b.x[e] = wmma::__float_to_tf32(b.x[e]);
                wmma::mma_sync(acc[0][nj], a0, b, acc[0][nj]);
                wmma::mma_sync(acc[1][nj], a1, b, acc[1][nj]);
            }
        }
        __syncthreads();
    }
    // ---- epilogue: stage fp32 tile in smem (As reused), store bf16 (no scaling) ----
    float* st = &As[0][0] + wid * 320;   // 16 rows x ld=20 per warp
    const int erow = lane >> 1;          // 2 lanes per row
    const int ecol = (lane & 1) * 8;     // 8 floats per lane
#pragma unroll
    for (int mi = 0; mi < 2; mi++) {
#pragma unroll
        for (int nj = 0; nj < 4; nj++) {
            wmma::store_matrix_sync(st, acc[mi][nj], 20, wmma::mem_row_major);
            __syncwarp();
            int r = row0 + wm * 32 + mi * 16 + erow;
            if (r < NN) {
                __nv_bfloat16 h[8];
#pragma unroll
                for (int q = 0; q < 8; q++)
                    h[q] = __float2bfloat16(st[erow * 20 + ecol + q]);
                *(uint4*)(g_Y1h + (size_t)r * 128 + wn * 64 + nj * 16 + ecol) = *(uint4*)h;
            }
            __syncwarp();
        }
    }
}

// Y2h[r] = bf16(sO[r] * (A1h @ W2)[r]);  A1h is bf16 h1 (relu already applied).
__global__ void __launch_bounds__(256) gemm2_kernel(const float* __restrict__ W) {
    __shared__ __align__(16) float As[128][36];
    __shared__ __align__(16) float Bs[32][68];
    const int tid = threadIdx.x;
    const int lane = tid & 31;
    const int wid = tid >> 5;
    const int wm = wid & 3;        // rows wm*32
    const int wn = wid >> 2;       // cols wn*32
    const int row0 = blockIdx.x * 128;

    wmma::fragment<wmma::accumulator, 16, 16, 8, float> acc[2][2];
#pragma unroll
    for (int mi = 0; mi < 2; mi++)
#pragma unroll
        for (int nj = 0; nj < 2; nj++) wmma::fill_fragment(acc[mi][nj], 0.f);

    for (int k0 = 0; k0 < 128; k0 += 32) {
        // A tile: 128x32 bf16 -> fp32; 1024 loads of 4 bf16 (8 B)
#pragma unroll
        for (int i = 0; i < 4; i++) {
            int idx = tid + i * 256;
            int r = idx >> 3;
            int c4 = idx & 7;
            int g = row0 + r;
            float4 v = make_float4(0.f, 0.f, 0.f, 0.f);
            if (g < NN) {
                uint2 u = *(const uint2*)(g_A1h + (size_t)g * 128 + k0 + c4 * 4);
                float2 f0 = __bfloat1622float2(*(__nv_bfloat162*)&u.x);
                float2 f1 = __bfloat1622float2(*(__nv_bfloat162*)&u.y);
                v = make_float4(f0.x, f0.y, f1.x, f1.y);
            }
            *(float4*)&As[r][c4 * 4] = v;
        }
        // B tile: 32x64 floats = 512 float4
#pragma unroll
        for (int i = 0; i < 2; i++) {
            int idx = tid + i * 256;
            int r = idx >> 4;
            int c4 = idx & 15;
            *(float4*)&Bs[r][c4 * 4] = *(const float4*)(W + (size_t)(k0 + r) * 64 + c4 * 4);
        }
        __syncthreads();
#pragma unroll
        for (int kk = 0; kk < 32; kk += 8) {
            wmma::fragment<wmma::matrix_a, 16, 16, 8, wmma::precision::tf32, wmma::row_major> a0, a1;
            wmma::load_matrix_sync(a0, &As[wm * 32][kk], 36);
            wmma::load_matrix_sync(a1, &As[wm * 32 + 16][kk], 36);
#pragma unroll
            for (int e = 0; e < a0.num_elements; e++) {
                a0.x[e] = wmma::__float_to_tf32(a0.x[e]);
                a1.x[e] = wmma::__float_to_tf32(a1.x[e]);
            }
#pragma unroll
            for (int nj = 0; nj < 2; nj++) {
                wmma::fragment<wmma::matrix_b, 16, 16, 8, wmma::precision::tf32, wmma::row_major> b;
                wmma::load_matrix_sync(b, &Bs[kk][wn * 32 + nj * 16], 68);
#pragma unroll
                for (int e = 0; e < b.num_elements; e++) b.x[e] = wmma::__float_to_tf32(b.x[e]);
                wmma::mma_sync(acc[0][nj], a0, b, acc[0][nj]);
                wmma::mma_sync(acc[1][nj], a1, b, acc[1][nj]);
            }
        }
        __syncthreads();
    }
    // ---- epilogue: scale by sO, store bf16 ----
    float* st = &As[0][0] + wid * 320;
    const int erow = lane >> 1;
    const int ecol = (lane & 1) * 8;
#pragma unroll
    for (int mi = 0; mi < 2; mi++) {
#pragma unroll
        for (int nj = 0; nj < 2; nj++) {
            wmma::store_matrix_sync(st, acc[mi][nj], 20, wmma::mem_row_major);
            __syncwarp();
            int r = row0 + wm * 32 + mi * 16 + erow;
            if (r < NN) {
                float so = g_sO[r];
                __nv_bfloat16 h[8];
#pragma unroll
                for (int q = 0; q < 8; q++)
                    h[q] = __float2bfloat16(st[erow * 20 + ecol + q] * so);
                *(uint4*)(g_Y2h + (size_t)r * 64 + wn * 32 + nj * 16 + ecol) = *(uint4*)h;
            }
            __syncwarp();
        }
    }
}

// ---------------- CSR gather aggregation (bf16 reads, fp32 accum) ----------------
// Layer 1: half-warp (16 lanes) per node; applies sO[src] per edge, then the
// full layer-1 epilogue: A1h[n] = bf16(relu(sI[n]*sum + b1)).
__global__ void __launch_bounds__(256) gather128_kernel(const float* __restrict__ b1) {
    int t = blockIdx.x * 256 + threadIdx.x;
    int n = t >> 4;
    int lane = t & 15;
    if (n >= NN) return;
    int j = g_rowoff[n];
    int end = g_rowoff[n + 1];
    const uint4* Y = (const uint4*)g_Y1h;   // row = 16 uint4
    float acc[8];
#pragma unroll
    for (int q = 0; q < 8; q++) acc[q] = 0.f;

    for (; j + 3 < end; j += 4) {
        int s0 = g_csrc[j], s1 = g_csrc[j + 1], s2 = g_csrc[j + 2], s3 = g_csrc[j + 3];
        float c0 = g_sO[s0], c1 = g_sO[s1], c2 = g_sO[s2], c3 = g_sO[s3];
        uint4 v0 = Y[(size_t)s0 * 16 + lane];
        uint4 v1 = Y[(size_t)s1 * 16 + lane];
        uint4 v2 = Y[(size_t)s2 * 16 + lane];
        uint4 v3 = Y[(size_t)s3 * 16 + lane];
        const __nv_bfloat162* p0 = (const __nv_bfloat162*)&v0;
        const __nv_bfloat162* p1 = (const __nv_bfloat162*)&v1;
        const __nv_bfloat162* p2 = (const __nv_bfloat162*)&v2;
        const __nv_bfloat162* p3 = (const __nv_bfloat162*)&v3;
#pragma unroll
        for (int q = 0; q < 4; q++) {
            float2 f0 = __bfloat1622float2(p0[q]);
            float2 f1 = __bfloat1622float2(p1[q]);
            float2 f2 = __bfloat1622float2(p2[q]);
            float2 f3 = __bfloat1622float2(p3[q]);
            acc[2 * q + 0] += c0 * f0.x + c1 * f1.x + c2 * f2.x + c3 * f3.x;
            acc[2 * q + 1] += c0 * f0.y + c1 * f1.y + c2 * f2.y + c3 * f3.y;
        }
    }
    for (; j < end; j++) {
        int s = g_csrc[j];
        float c = g_sO[s];
        uint4 v = Y[(size_t)s * 16 + lane];
        const __nv_bfloat162* p = (const __nv_bfloat162*)&v;
#pragma unroll
        for (int q = 0; q < 4; q++) {
            float2 f = __bfloat1622float2(p[q]);
            acc[2 * q + 0] += c * f.x;
            acc[2 * q + 1] += c * f.y;
        }
    }
    // Layer-1 epilogue fused: h1 = relu(sI*sum + b1), stored bf16.
    float si = g_sI[n];
    __nv_bfloat16 h[8];
#pragma unroll
    for (int q = 0; q < 8; q++) {
        float v = fmaf(acc[q], si, b1[lane * 8 + q]);
        h[q] = __float2bfloat16(fmaxf(v, 0.f));
    }
    *(uint4*)(g_A1h + (size_t)n * 128 + lane * 8) = *(uint4*)h;
}

// Layer 2 aggregation fused with pooling: 8 lanes per node; computes the node's
// final features relu(sI*sum + b2) in-register and reduces into per-graph sums
// via a block-local smem stage (nodes are gid-sorted; a 32-node block spans a
// handful of graphs). No M2 array, no separate pool kernel.
__global__ void __launch_bounds__(256) gather64_pool_kernel(const int* __restrict__ gids,
                                                            const float* __restrict__ b2) {
    __shared__ float sacc[4][64];
    {
        int s = threadIdx.x >> 6, c = threadIdx.x & 63;
        sacc[s][c] = 0.f;
    }
    __syncthreads();

    int t = blockIdx.x * 256 + threadIdx.x;
    int n = t >> 3;
    int lane = t & 7;
    int n0 = blockIdx.x * 32;           // first node of this block
    int g0 = gids[n0 < NN ? n0 : NN - 1];

    if (n < NN) {
        int j = g_rowoff[n];
        int end = g_rowoff[n + 1];
        const uint4* Y = (const uint4*)g_Y2h;   // row = 8 uint4
        float acc[8];
#pragma unroll
        for (int q = 0; q < 8; q++) acc[q] = 0.f;

        for (; j + 3 < end; j += 4) {
            int s0 = g_csrc[j], s1 = g_csrc[j + 1], s2 = g_csrc[j + 2], s3 = g_csrc[j + 3];
            uint4 v0 = Y[(size_t)s0 * 8 + lane];
            uint4 v1 = Y[(size_t)s1 * 8 + lane];
            uint4 v2 = Y[(size_t)s2 * 8 + lane];
            uint4 v3 = Y[(size_t)s3 * 8 + lane];
            const __nv_bfloat162* p0 = (const __nv_bfloat162*)&v0;
            const __nv_bfloat162* p1 = (const __nv_bfloat162*)&v1;
            const __nv_bfloat162* p2 = (const __nv_bfloat162*)&v2;
            const __nv_bfloat162* p3 = (const __nv_bfloat162*)&v3;
#pragma unroll
            for (int q = 0; q < 4; q++) {
                float2 f0 = __bfloat1622float2(p0[q]);
                float2 f1 = __bfloat1622float2(p1[q]);
                float2 f2 = __bfloat1622float2(p2[q]);
                float2 f3 = __bfloat1622float2(p3[q]);
                acc[2 * q + 0] += (f0.x + f1.x) + (f2.x + f3.x);
                acc[2 * q + 1] += (f0.y + f1.y) + (f2.y + f3.y);
            }
        }
        for (; j < end; j++) {
            int s = g_csrc[j];
            uint4 v = Y[(size_t)s * 8 + lane];
            const __nv_bfloat162* p = (const __nv_bfloat162*)&v;
#pragma unroll
            for (int q = 0; q < 4; q++) {
                float2 f = __bfloat1622float2(p[q]);
                acc[2 * q + 0] += f.x;
                acc[2 * q + 1] += f.y;
            }
        }
        // Node epilogue + pooling accumulation
        float si = g_sI[n];
        int gid = gids[n];
        int slot = gid - g0;
#pragma unroll
        for (int q = 0; q < 8; q++) {
            float v = fmaxf(fmaf(acc[q], si, b2[lane * 8 + q]), 0.f);
            if (slot < 4) atomicAdd(&sacc[slot][lane * 8 + q], v);
            else          atomicAdd(&g_pooled[gid * 64 + lane * 8 + q], v);
        }
    }
    __syncthreads();
    int slot = threadIdx.x >> 6, col = threadIdx.x & 63;
    int gg = g0 + slot;
    float v = sacc[slot][col];
    if (gg < NG && v != 0.f) atomicAdd(&g_pooled[gg * 64 + col], v);
}

// ---------------- head: per-graph mean + MLP + softmax ----------------
__global__ void __launch_bounds__(128) head_kernel(const int* __restrict__ gids,
                                                   const float* __restrict__ fcW1,
                                                   const float* __restrict__ fcb1,
                                                   const float* __restrict__ fcW2,
                                                   const float* __restrict__ fcb2,
                                                   float* __restrict__ out) {
    __shared__ float w1s[OF * HID];
    __shared__ float w2s[HID * NCLS];
    for (int i = threadIdx.x; i < OF * HID; i += blockDim.x) w1s[i] = fcW1[i];
    for (int i = threadIdx.x; i < HID * NCLS; i += blockDim.x) w2s[i] = fcW2[i];
    __syncthreads();

    int g = threadIdx.x;
    if (g >= NG) return;

    // node count for graph g via binary search on sorted gids
    int lo = 0, hi = NN;
    while (lo < hi) { int mid = (lo + hi) >> 1; if (gids[mid] < g) lo = mid + 1; else hi = mid; }
    int start = lo;
    hi = NN;
    while (lo < hi) { int mid = (lo + hi) >> 1; if (gids[mid] < g + 1) lo = mid + 1; else hi = mid; }
    int cnt = lo - start;
    float inv_c = 1.f / (float)(cnt > 0 ? cnt : 1);

    float x[OF];
#pragma unroll
    for (int c = 0; c < OF; c++) x[c] = g_pooled[g * 64 + c] * inv_c;
    float z[HID];
#pragma unroll
    for (int h = 0; h < HID; h++) {
        float s = fcb1[h];
#pragma unroll
        for (int c = 0; c < OF; c++) s = fmaf(x[c], w1s[c * HID + h], s);
        z[h] = fmaxf(s, 0.f);
    }
    float o[NCLS];
    float mx = -1e30f;
#pragma unroll
    for (int k = 0; k < NCLS; k++) {
        float s = fcb2[k];
#pragma unroll
        for (int h = 0; h < HID; h++) s = fmaf(z[h], w2s[h * NCLS + k], s);
        o[k] = s;
        mx = fmaxf(mx, s);
    }
    float sum = 0.f;
#pragma unroll
    for (int k = 0; k < NCLS; k++) { o[k] = expf(o[k] - mx); sum += o[k]; }
    float inv = 1.f / sum;
#pragma unroll
    for (int k = 0; k < NCLS; k++) out[g * NCLS + k] = o[k] * inv;
}

// ---------------- launch ----------------
extern "C" void kernel_launch(void* const* d_in, const int* in_sizes, int n_in,
                              void* d_out, int out_size) {
    const float* feats = (const float*)d_in[0];
    const int*   src   = (const int*)d_in[1];
    const int*   dst   = (const int*)d_in[2];
    const int*   gids  = (const int*)d_in[3];
    const float* W1    = (const float*)d_in[4];
    const float* b1    = (const float*)d_in[5];
    const float* W2    = (const float*)d_in[6];
    const float* b2    = (const float*)d_in[7];
    const float* fcW1  = (const float*)d_in[8];
    const float* fcb1  = (const float*)d_in[9];
    const float* fcW2  = (const float*)d_in[10];
    const float* fcb2  = (const float*)d_in[11];
    float* out = (float*)d_out;

    // Side stream + fork/join events (created once on the non-capturing
    // correctness call; reused during capture). Identical launches every call.
    static cudaStream_t s2 = nullptr;
    static cudaEvent_t evFork = nullptr, evJoin = nullptr;
    if (s2 == nullptr) {
        cudaStreamCreateWithFlags(&s2, cudaStreamNonBlocking);
        cudaEventCreateWithFlags(&evFork, cudaEventDisableTiming);
        cudaEventCreateWithFlags(&evJoin, cudaEventDisableTiming);
    }

    // Fork: gemm1 (feats@W1 -> bf16, unscaled) is independent of the CSR build.
    cudaEventRecord(evFork, 0);
    cudaStreamWaitEvent(s2, evFork, 0);
    gemm1_kernel<<<(NN + 127) / 128, 256, 0, s2>>>(feats, W1);
    cudaEventRecord(evJoin, s2);

    // Main stream: degrees, CSR row offsets (2-kernel scan), scales, CSR fill
    zero_deg_kernel<<<(NN + 255) / 256, 256>>>();
    degree_kernel<<<(NE + 255) / 256, 256>>>(src, dst);
    scan_phase1<<<SCAN_NB, 1024>>>();
    scan_phase3<<<SCAN_NB, 1024>>>();
    fill_kernel<<<(NE + 255) / 256, 256>>>(src, dst);

    // Join: gather needs both Y1h (s2) and the CSR (main stream).
    cudaStreamWaitEvent(0, evJoin, 0);

    // Layer 1 aggregation + epilogue fused: A1h = bf16(relu(sI .* (A·sO·Y1) + b1))
    gather128_kernel<<<(NN * 16 + 255) / 256, 256>>>(b1);

    // Layer 2 GEMM: Y2h = bf16(sO .* (A1h @ W2))
    gemm2_kernel<<<(NN + 127) / 128, 256>>>(W2);

    // Layer 2 aggregation + node epilogue + per-graph pooling (fused)
    gather64_pool_kernel<<<(NN * 8 + 255) / 256, 256>>>(gids, b2);

    // Head: mean (counts via binary search) + MLP + softmax
    head_kernel<<<1, 128>>>(gids, fcW1, fcb1, fcW2, fcb2, out);
}

// round 15
// speedup vs baseline: 1.9468x; 1.0051x over previous
#include <cuda_runtime.h>
#include <cuda_bf16.h>
#include <cuda_fp16.h>
#include <cuda_fp8.h>
#include <mma.h>
#include <math.h>

using namespace nvcuda;

// Problem constants (match reference setup_inputs)
#define NN 100000      // nodes
#define NE 1600000     // edges
#define NG 128         // graphs
#define INF 128
#define HF  128
#define OF  64
#define HID 10
#define NCLS 10

#define SCAN_NB ((NN + 1023) / 1024)   // 98 blocks for the node scan

// ---------------- scratch (device globals; allocation-free) ----------------
__device__ __align__(128) unsigned char  g_Y1f[(size_t)NN * 128]; // fp8 e4m3 (feats@W1), UNscaled
__device__ __align__(128) __nv_bfloat16 g_A1h[(size_t)NN * 128];  // bf16(relu(sI.*M1+b1)) = h1
__device__ __align__(128) __nv_bfloat16 g_Y2h[(size_t)NN * 64];   // bf16(sO .* (h1@W2))
__device__ int   g_degO[NN];
__device__ int   g_degI[NN];
__device__ float g_sO[NN];
__device__ float g_sI[NN];
__device__ int   g_rowoff[NN + 1];   // CSR row offsets (by dst)
__device__ int   g_cursor[NN];       // fill cursors
__device__ int   g_csrc[NE];         // CSR column indices = src per dst-sorted edge
__device__ unsigned long long g_look[128]; // decoupled-lookback state (flag|value)
__device__ float g_pooled[NG * 64];  // per-graph sums (atomics)

// ---------------- helpers ----------------
__device__ __forceinline__ float2 fp8x2_to_f2(unsigned short s) {
    __half2_raw h = __nv_cvt_fp8x2_to_halfraw2((__nv_fp8x2_storage_t)s, __NV_E4M3);
    return __half22float2(*reinterpret_cast<__half2*>(&h));
}

// ---------------- setup kernels ----------------
__global__ void zero_deg_kernel() {
    int i = blockIdx.x * 256 + threadIdx.x;
    if (i < NN) { g_degO[i] = 0; g_degI[i] = 0; }
    if (i < NG * 64) g_pooled[i] = 0.f;
    if (i < 128) g_look[i] = 0ull;
}

__global__ void degree_kernel(const int* __restrict__ src, const int* __restrict__ dst) {
    int i = blockIdx.x * 256 + threadIdx.x;
    if (i < NE) {
        atomicAdd(&g_degO[src[i]], 1);
        atomicAdd(&g_degI[dst[i]], 1);
    }
}

// Single-kernel scan with decoupled lookback (98 blocks = one wave, all resident).
// Writes rowoff/cursor + normalization scales.
#define LOOK_AGG  (1ull << 62)
#define LOOK_PREF (1ull << 63)
__global__ void __launch_bounds__(1024) scan_fused() {
    int i = blockIdx.x * 1024 + threadIdx.x;
    int v = (i < NN) ? g_degI[i] : 0;
    __shared__ int ps[1024];
    __shared__ int s_ex;
    ps[threadIdx.x] = v;
    __syncthreads();
#pragma unroll
    for (int off = 1; off < 1024; off <<= 1) {
        int t = (threadIdx.x >= off) ? ps[threadIdx.x - off] : 0;
        __syncthreads();
        ps[threadIdx.x] += t;
        __syncthreads();
    }
    // publish this block's aggregate
    if (threadIdx.x == 1023)
        atomicExch(&g_look[blockIdx.x], LOOK_AGG | (unsigned long long)(unsigned)ps[1023]);
    // lookback: sum predecessor aggregates until an inclusive prefix is found
    if (threadIdx.x == 0) {
        int ex = 0;
        for (int b = blockIdx.x - 1; b >= 0; b--) {
            unsigned long long x;
            do { x = atomicAdd(&g_look[b], 0ull); } while (x == 0ull);
            ex += (int)(unsigned)(x & 0xFFFFFFFFull);
            if (x & LOOK_PREF) break;
        }
        s_ex = ex;
    }
    __syncthreads();
    int ex0 = s_ex;
    if (threadIdx.x == 1023) {
        atomicExch(&g_look[blockIdx.x],
                   LOOK_PREF | (unsigned long long)(unsigned)(ex0 + ps[1023]));
        if (blockIdx.x == SCAN_NB - 1) g_rowoff[NN] = ex0 + ps[1023];
    }
    if (i < NN) {
        int d = g_degI[i];
        int ex = ex0 + ps[threadIdx.x] - d;
        g_rowoff[i] = ex;
        g_cursor[i] = ex;
        g_sO[i] = rsqrtf(fmaxf((float)g_degO[i], 1.f));
        g_sI[i] = rsqrtf(fmaxf((float)d, 1.f));
    }
}

__global__ void fill_kernel(const int* __restrict__ src, const int* __restrict__ dst) {
    int e = blockIdx.x * 256 + threadIdx.x;
    if (e < NE) {
        int d = dst[e];
        int p = atomicAdd(&g_cursor[d], 1);
        g_csrc[p] = src[e];
    }
}

// ---------------- tf32 WMMA GEMMs ----------------
// Y1f[r] = fp8_e4m3((feats @ W1)[r])   -- UNscaled; sO applied in gather128.
// Independent of the CSR/degree chain -> runs on a side stream.
__global__ void __launch_bounds__(256) gemm1_kernel(const float* __restrict__ X,
                                                    const float* __restrict__ W) {
    __shared__ __align__(16) float As[128][36];   // reused as epilogue staging
    __shared__ __align__(16) float Bs[32][132];
    const int tid = threadIdx.x;
    const int lane = tid & 31;
    const int wid = tid >> 5;
    const int wm = wid & 3;        // 0..3  -> rows wm*32
    const int wn = wid >> 2;       // 0..1  -> cols wn*64
    const int row0 = blockIdx.x * 128;

    wmma::fragment<wmma::accumulator, 16, 16, 8, float> acc[2][4];
#pragma unroll
    for (int mi = 0; mi < 2; mi++)
#pragma unroll
        for (int nj = 0; nj < 4; nj++) wmma::fill_fragment(acc[mi][nj], 0.f);

    for (int k0 = 0; k0 < 128; k0 += 32) {
        // A tile: 128x32 floats = 1024 float4
#pragma unroll
        for (int i = 0; i < 4; i++) {
            int idx = tid + i * 256;
            int r = idx >> 3;
            int c4 = idx & 7;
            int g = row0 + r;
            float4 v = make_float4(0.f, 0.f, 0.f, 0.f);
            if (g < NN) v = *(const float4*)(X + (size_t)g * 128 + k0 + c4 * 4);
            *(float4*)&As[r][c4 * 4] = v;
        }
        // B tile: 32x128 floats
#pragma unroll
        for (int i = 0; i < 4; i++) {
            int idx = tid + i * 256;
            int r = idx >> 5;
            int c4 = idx & 31;
            *(float4*)&Bs[r][c4 * 4] = *(const float4*)(W + (size_t)(k0 + r) * 128 + c4 * 4);
        }
        __syncthreads();
#pragma unroll
        for (int kk = 0; kk < 32; kk += 8) {
            wmma::fragment<wmma::matrix_a, 16, 16, 8, wmma::precision::tf32, wmma::row_major> a0, a1;
            wmma::load_matrix_sync(a0, &As[wm * 32][kk], 36);
            wmma::load_matrix_sync(a1, &As[wm * 32 + 16][kk], 36);
#pragma unroll
            for (int e = 0; e < a0.num_elements; e++) {
                a0.x[e] = wmma::__float_to_tf32(a0.x[e]);
                a1.x[e] = wmma::__float_to_tf32(a1.x[e]);
            }
#pragma unroll
            for (int nj = 0; nj < 4; nj++) {
                wmma::fragment<wmma::matrix_b, 16, 16, 8, wmma::precision::tf32, wmma::row_major> b;
                wmma::load_matrix_sync(b, &Bs[kk][wn * 64 + nj * 16], 132);
#pragma unroll
                for (int e = 0; e < b.num_elements; e++) b.x[e] = wmma::__float_to_tf32(b.x[e]);
                wmma::mma_sync(acc[0][nj], a0, b, acc[0][nj]);
                wmma::mma_sync(acc[1][nj], a1, b, acc[1][nj]);
            }
        }
        __syncthreads();
    }
    // ---- epilogue: stage fp32 tile in smem (As reused), store fp8 e4m3 ----
    float* st = &As[0][0] + wid * 320;   // 16 rows x ld=20 per warp
    const int erow = lane >> 1;          // 2 lanes per row
    const int ecol = (lane & 1) * 8;     // 8 floats per lane
#pragma unroll
    for (int mi = 0; mi < 2; mi++) {
#pragma unroll
        for (int nj = 0; nj < 4; nj++) {
            wmma::store_matrix_sync(st, acc[mi][nj], 20, wmma::mem_row_major);
            __syncwarp();
            int r = row0 + wm * 32 + mi * 16 + erow;
            if (r < NN) {
                const float* p = st + erow * 20 + ecol;
                unsigned int e0 = (unsigned int)__nv_cvt_float2_to_fp8x2(
                    make_float2(p[0], p[1]), __NV_SATFINITE, __NV_E4M3);
                unsigned int e1 = (unsigned int)__nv_cvt_float2_to_fp8x2(
                    make_float2(p[2], p[3]), __NV_SATFINITE, __NV_E4M3);
                unsigned int e2 = (unsigned int)__nv_cvt_float2_to_fp8x2(
                    make_float2(p[4], p[5]), __NV_SATFINITE, __NV_E4M3);
                unsigned int e3 = (unsigned int)__nv_cvt_float2_to_fp8x2(
                    make_float2(p[6], p[7]), __NV_SATFINITE, __NV_E4M3);
                uint2 o;
                o.x = e0 | (e1 << 16);
                o.y = e2 | (e3 << 16);
                *(uint2*)(g_Y1f + (size_t)r * 128 + wn * 64 + nj * 16 + ecol) = o;
            }
            __syncwarp();
        }
    }
}

// Y2h[r] = bf16(sO[r] * (A1h @ W2)[r]);  A1h is bf16 h1 (relu already applied).
__global__ void __launch_bounds__(256) gemm2_kernel(const float* __restrict__ W) {
    __shared__ __align__(16) float As[128][36];
    __shared__ __align__(16) float Bs[32][68];
    const int tid = threadIdx.x;
    const int lane = tid & 31;
    const int wid = tid >> 5;
    const int wm = wid & 3;        // rows wm*32
    const int wn = wid >> 2;       // cols wn*32
    const int row0 = blockIdx.x * 128;

    wmma::fragment<wmma::accumulator, 16, 16, 8, float> acc[2][2];
#pragma unroll
    for (int mi = 0; mi < 2; mi++)
#pragma unroll
        for (int nj = 0; nj < 2; nj++) wmma::fill_fragment(acc[mi][nj], 0.f);

    for (int k0 = 0; k0 < 128; k0 += 32) {
        // A tile: 128x32 bf16 -> fp32; 512 uint4 loads (8 bf16 each)
#pragma unroll
        for (int i = 0; i < 2; i++) {
            int idx = tid + i * 256;       // 0..511
            int r = idx >> 2;              // 4 uint4 per row-chunk
            int c8 = idx & 3;
            int g = row0 + r;
            float4 va = make_float4(0.f, 0.f, 0.f, 0.f);
            float4 vb = va;
            if (g < NN) {
                uint4 u = *(const uint4*)(g_A1h + (size_t)g * 128 + k0 + c8 * 8);
                float2 f0 = __bfloat1622float2(*(__nv_bfloat162*)&u.x);
                float2 f1 = __bfloat1622float2(*(__nv_bfloat162*)&u.y);
                float2 f2 = __bfloat1622float2(*(__nv_bfloat162*)&u.z);
                float2 f3 = __bfloat1622float2(*(__nv_bfloat162*)&u.w);
                va = make_float4(f0.x, f0.y, f1.x, f1.y);
                vb = make_float4(f2.x, f2.y, f3.x, f3.y);
            }
            *(float4*)&As[r][c8 * 8 + 0] = va;
            *(float4*)&As[r][c8 * 8 + 4] = vb;
        }
        // B tile: 32x64 floats = 512 float4
#pragma unroll
        for (int i = 0; i < 2; i++) {
            int idx = tid + i * 256;
            int r = idx >> 4;
            int c4 = idx & 15;
            *(float4*)&Bs[r][c4 * 4] = *(const float4*)(W + (size_t)(k0 + r) * 64 + c4 * 4);
        }
        __syncthreads();
#pragma unroll
        for (int kk = 0; kk < 32; kk += 8) {
            wmma::fragment<wmma::matrix_a, 16, 16, 8, wmma::precision::tf32, wmma::row_major> a0, a1;
            wmma::load_matrix_sync(a0, &As[wm * 32][kk], 36);
            wmma::load_matrix_sync(a1, &As[wm * 32 + 16][kk], 36);
#pragma unroll
            for (int e = 0; e < a0.num_elements; e++) {
                a0.x[e] = wmma::__float_to_tf32(a0.x[e]);
                a1.x[e] = wmma::__float_to_tf32(a1.x[e]);
            }
#pragma unroll
            for (int nj = 0; nj < 2; nj++) {
                wmma::fragment<wmma::matrix_b, 16, 16, 8, wmma::precision::tf32, wmma::row_major> b;
                wmma::load_matrix_sync(b, &Bs[kk][wn * 32 + nj * 16], 68);
#pragma unroll
                for (int e = 0; e < b.num_elements; e++) b.x[e] = wmma::__float_to_tf32(b.x[e]);
                wmma::mma_sync(acc[0][nj], a0, b, acc[0][nj]);
                wmma::mma_sync(acc[1][nj], a1, b, acc[1][nj]);
            }
        }
        __syncthreads();
    }
    // ---- epilogue: scale by sO, store bf16 ----
    float* st = &As[0][0] + wid * 320;
    const int erow = lane >> 1;
    const int ecol = (lane & 1) * 8;
#pragma unroll
    for (int mi = 0; mi < 2; mi++) {
#pragma unroll
        for (int nj = 0; nj < 2; nj++) {
            wmma::store_matrix_sync(st, acc[mi][nj], 20, wmma::mem_row_major);
            __syncwarp();
            int r = row0 + wm * 32 + mi * 16 + erow;
            if (r < NN) {
                float so = g_sO[r];
                __nv_bfloat16 h[8];
#pragma unroll
                for (int q = 0; q < 8; q++)
                    h[q] = __float2bfloat16(st[erow * 20 + ecol + q] * so);
                *(uint4*)(g_Y2h + (size_t)r * 64 + wn * 32 + nj * 16 + ecol) = *(uint4*)h;
            }
            __syncwarp();
        }
    }
}

// ---------------- CSR gather aggregation ----------------
// Layer 1: half-warp (16 lanes) per node; fp8 rows (128 B = 1 L2 line),
// lane loads uint2 = 8 fp8. Applies sO[src] per edge, then the full layer-1
// epilogue: A1h[n] = bf16(relu(sI[n]*sum + b1)).
__global__ void __launch_bounds__(256) gather128_kernel(const float* __restrict__ b1) {
    int t = blockIdx.x * 256 + threadIdx.x;
    int n = t >> 4;
    int lane = t & 15;
    if (n >= NN) return;
    int j = g_rowoff[n];
    int end = g_rowoff[n + 1];
    const uint2* Y = (const uint2*)g_Y1f;   // row = 16 uint2
    float acc[8];
#pragma unroll
    for (int q = 0; q < 8; q++) acc[q] = 0.f;

    for (; j + 3 < end; j += 4) {
        int s0 = g_csrc[j], s1 = g_csrc[j + 1], s2 = g_csrc[j + 2], s3 = g_csrc[j + 3];
        float c0 = g_sO[s0], c1 = g_sO[s1], c2 = g_sO[s2], c3 = g_sO[s3];
        uint2 u0 = Y[(size_t)s0 * 16 + lane];
        uint2 u1 = Y[(size_t)s1 * 16 + lane];
        uint2 u2 = Y[(size_t)s2 * 16 + lane];
        uint2 u3 = Y[(size_t)s3 * 16 + lane];
#pragma unroll
        for (int e = 0; e < 4; e++) {
            uint2 u = (e == 0) ? u0 : (e == 1) ? u1 : (e == 2) ? u2 : u3;
            float c = (e == 0) ? c0 : (e == 1) ? c1 : (e == 2) ? c2 : c3;
            float2 f0 = fp8x2_to_f2((unsigned short)(u.x & 0xFFFF));
            float2 f1 = fp8x2_to_f2((unsigned short)(u.x >> 16));
            float2 f2 = fp8x2_to_f2((unsigned short)(u.y & 0xFFFF));
            float2 f3 = fp8x2_to_f2((unsigned short)(u.y >> 16));
            acc[0] = fmaf(c, f0.x, acc[0]);
            acc[1] = fmaf(c, f0.y, acc[1]);
            acc[2] = fmaf(c, f1.x, acc[2]);
            acc[3] = fmaf(c, f1.y, acc[3]);
            acc[4] = fmaf(c, f2.x, acc[4]);
            acc[5] = fmaf(c, f2.y, acc[5]);
            acc[6] = fmaf(c, f3.x, acc[6]);
            acc[7] = fmaf(c, f3.y, acc[7]);
        }
    }
    for (; j < end; j++) {
        int s = g_csrc[j];
        float c = g_sO[s];
        uint2 u = Y[(size_t)s * 16 + lane];
        float2 f0 = fp8x2_to_f2((unsigned short)(u.x & 0xFFFF));
        float2 f1 = fp8x2_to_f2((unsigned short)(u.x >> 16));
        float2 f2 = fp8x2_to_f2((unsigned short)(u.y & 0xFFFF));
        float2 f3 = fp8x2_to_f2((unsigned short)(u.y >> 16));
        acc[0] = fmaf(c, f0.x, acc[0]);
        acc[1] = fmaf(c, f0.y, acc[1]);
        acc[2] = fmaf(c, f1.x, acc[2]);
        acc[3] = fmaf(c, f1.y, acc[3]);
        acc[4] = fmaf(c, f2.x, acc[4]);
        acc[5] = fmaf(c, f2.y, acc[5]);
        acc[6] = fmaf(c, f3.x, acc[6]);
        acc[7] = fmaf(c, f3.y, acc[7]);
    }
    // Layer-1 epilogue fused: h1 = relu(sI*sum + b1), stored bf16.
    float si = g_sI[n];
    __nv_bfloat16 h[8];
#pragma unroll
    for (int q = 0; q < 8; q++) {
        float v = fmaf(acc[q], si, b1[lane * 8 + q]);
        h[q] = __float2bfloat16(fmaxf(v, 0.f));
    }
    *(uint4*)(g_A1h + (size_t)n * 128 + lane * 8) = *(uint4*)h;
}

// Layer 2 aggregation fused with pooling: 8 lanes per node; computes the node's
// final features relu(sI*sum + b2) in-register and reduces into per-graph sums
// via a block-local smem stage (gid-sorted nodes). No M2 array, no pool kernel.
__global__ void __launch_bounds__(256) gather64_pool_kernel(const int* __restrict__ gids,
                                                            const float* __restrict__ b2) {
    __shared__ float sacc[4][64];
    {
        int s = threadIdx.x >> 6, c = threadIdx.x & 63;
        sacc[s][c] = 0.f;
    }
    __syncthreads();

    int t = blockIdx.x * 256 + threadIdx.x;
    int n = t >> 3;
    int lane = t & 7;
    int n0 = blockIdx.x * 32;           // first node of this block
    int g0 = gids[n0 < NN ? n0 : NN - 1];

    if (n < NN) {
        int j = g_rowoff[n];
        int end = g_rowoff[n + 1];
        const uint4* Y = (const uint4*)g_Y2h;   // row = 8 uint4
        float acc[8];
#pragma unroll
        for (int q = 0; q < 8; q++) acc[q] = 0.f;

        for (; j + 3 < end; j += 4) {
            int s0 = g_csrc[j], s1 = g_csrc[j + 1], s2 = g_csrc[j + 2], s3 = g_csrc[j + 3];
            uint4 v0 = Y[(size_t)s0 * 8 + lane];
            uint4 v1 = Y[(size_t)s1 * 8 + lane];
            uint4 v2 = Y[(size_t)s2 * 8 + lane];
            uint4 v3 = Y[(size_t)s3 * 8 + lane];
            const __nv_bfloat162* p0 = (const __nv_bfloat162*)&v0;
            const __nv_bfloat162* p1 = (const __nv_bfloat162*)&v1;
            const __nv_bfloat162* p2 = (const __nv_bfloat162*)&v2;
            const __nv_bfloat162* p3 = (const __nv_bfloat162*)&v3;
#pragma unroll
            for (int q = 0; q < 4; q++) {
                float2 f0 = __bfloat1622float2(p0[q]);
                float2 f1 = __bfloat1622float2(p1[q]);
                float2 f2 = __bfloat1622float2(p2[q]);
                float2 f3 = __bfloat1622float2(p3[q]);
                acc[2 * q + 0] += (f0.x + f1.x) + (f2.x + f3.x);
                acc[2 * q + 1] += (f0.y + f1.y) + (f2.y + f3.y);
            }
        }
        for (; j < end; j++) {
            int s = g_csrc[j];
            uint4 v = Y[(size_t)s * 8 + lane];
            const __nv_bfloat162* p = (const __nv_bfloat162*)&v;
#pragma unroll
            for (int q = 0; q < 4; q++) {
                float2 f = __bfloat1622float2(p[q]);
                acc[2 * q + 0] += f.x;
                acc[2 * q + 1] += f.y;
            }
        }
        // Node epilogue + pooling accumulation
        float si = g_sI[n];
        int gid = gids[n];
        int slot = gid - g0;
#pragma unroll
        for (int q = 0; q < 8; q++) {
            float v = fmaxf(fmaf(acc[q], si, b2[lane * 8 + q]), 0.f);
            if (slot < 4) atomicAdd(&sacc[slot][lane * 8 + q], v);
            else          atomicAdd(&g_pooled[gid * 64 + lane * 8 + q], v);
        }
    }
    __syncthreads();
    int slot = threadIdx.x >> 6, col = threadIdx.x & 63;
    int gg = g0 + slot;
    float v = sacc[slot][col];
    if (gg < NG && v != 0.f) atomicAdd(&g_pooled[gg * 64 + col], v);
}

// ---------------- head: per-graph mean + MLP + softmax ----------------
__global__ void __launch_bounds__(128) head_kernel(const int* __restrict__ gids,
                                                   const float* __restrict__ fcW1,
                                                   const float* __restrict__ fcb1,
                                                   const float* __restrict__ fcW2,
                                                   const float* __restrict__ fcb2,
                                                   float* __restrict__ out) {
    __shared__ float w1s[OF * HID];
    __shared__ float w2s[HID * NCLS];
    for (int i = threadIdx.x; i < OF * HID; i += blockDim.x) w1s[i] = fcW1[i];
    for (int i = threadIdx.x; i < HID * NCLS; i += blockDim.x) w2s[i] = fcW2[i];
    __syncthreads();

    int g = threadIdx.x;
    if (g >= NG) return;

    // node count for graph g via binary search on sorted gids
    int lo = 0, hi = NN;
    while (lo < hi) { int mid = (lo + hi) >> 1; if (gids[mid] < g) lo = mid + 1; else hi = mid; }
    int start = lo;
    hi = NN;
    while (lo < hi) { int mid = (lo + hi) >> 1; if (gids[mid] < g + 1) lo = mid + 1; else hi = mid; }
    int cnt = lo - start;
    float inv_c = 1.f / (float)(cnt > 0 ? cnt : 1);

    float x[OF];
#pragma unroll
    for (int c = 0; c < OF; c++) x[c] = g_pooled[g * 64 + c] * inv_c;
    float z[HID];
#pragma unroll
    for (int h = 0; h < HID; h++) {
        float s = fcb1[h];
#pragma unroll
        for (int c = 0; c < OF; c++) s = fmaf(x[c], w1s[c * HID + h], s);
        z[h] = fmaxf(s, 0.f);
    }
    float o[NCLS];
    float mx = -1e30f;
#pragma unroll
    for (int k = 0; k < NCLS; k++) {
        float s = fcb2[k];
#pragma unroll
        for (int h = 0; h < HID; h++) s = fmaf(z[h], w2s[h * NCLS + k], s);
        o[k] = s;
        mx = fmaxf(mx, s);
    }
    float sum = 0.f;
#pragma unroll
    for (int k = 0; k < NCLS; k++) { o[k] = expf(o[k] - mx); sum += o[k]; }
    float inv = 1.f / sum;
#pragma unroll
    for (int k = 0; k < NCLS; k++) out[g * NCLS + k] = o[k] * inv;
}

// ---------------- launch ----------------
extern "C" void kernel_launch(void* const* d_in, const int* in_sizes, int n_in,
                              void* d_out, int out_size) {
    const float* feats = (const float*)d_in[0];
    const int*   src   = (const int*)d_in[1];
    const int*   dst   = (const int*)d_in[2];
    const int*   gids  = (const int*)d_in[3];
    const float* W1    = (const float*)d_in[4];
    const float* b1    = (const float*)d_in[5];
    const float* W2    = (const float*)d_in[6];
    const float* b2    = (const float*)d_in[7];
    const float* fcW1  = (const float*)d_in[8];
    const float* fcb1  = (const float*)d_in[9];
    const float* fcW2  = (const float*)d_in[10];
    const float* fcb2  = (const float*)d_in[11];
    float* out = (float*)d_out;

    // Side stream + fork/join events (created once on the non-capturing
    // correctness call; reused during capture). Identical launches every call.
    static cudaStream_t s2 = nullptr;
    static cudaEvent_t evFork = nullptr, evJoin = nullptr;
    if (s2 == nullptr) {
        cudaStreamCreateWithFlags(&s2, cudaStreamNonBlocking);
        cudaEventCreateWithFlags(&evFork, cudaEventDisableTiming);
        cudaEventCreateWithFlags(&evJoin, cudaEventDisableTiming);
    }

    // Fork point recorded first: gemm1 (on s2) has no deps on the CSR chain,
    // so it executes concurrently with it regardless of submission order.
    cudaEventRecord(evFork, 0);

    // Main stream: degrees, CSR row offsets (single lookback scan), scales, fill
    zero_deg_kernel<<<(NN + 255) / 256, 256>>>();
    degree_kernel<<<(NE + 255) / 256, 256>>>(src, dst);
    scan_fused<<<SCAN_NB, 1024>>>();
    fill_kernel<<<(NE + 255) / 256, 256>>>(src, dst);

    // Side stream: Y1f = fp8(feats @ W1), unscaled
    cudaStreamWaitEvent(s2, evFork, 0);
    gemm1_kernel<<<(NN + 127) / 128, 256, 0, s2>>>(feats, W1);
    cudaEventRecord(evJoin, s2);

    // Join: gather needs both Y1f (s2) and the CSR (main stream).
    cudaStreamWaitEvent(0, evJoin, 0);

    // Layer 1 aggregation + epilogue fused: A1h = bf16(relu(sI .* (A·sO·Y1) + b1))
    gather128_kernel<<<(NN * 16 + 255) / 256, 256>>>(b1);

    // Layer 2 GEMM: Y2h = bf16(sO .* (A1h @ W2))
    gemm2_kernel<<<(NN + 127) / 128, 256>>>(W2);

    // Layer 2 aggregation + node epilogue + per-graph pooling (fused)
    gather64_pool_kernel<<<(NN * 8 + 255) / 256, 256>>>(gids, b2);

    // Head: mean (counts via binary search) + MLP + softmax
    head_kernel<<<1, 128>>>(gids, fcW1, fcb1, fcW2, fcb2, out);
}

// round 16
// speedup vs baseline: 1.9824x; 1.0183x over previous
#include <cuda_runtime.h>
#include <cuda_bf16.h>
#include <cuda_fp16.h>
#include <cuda_fp8.h>
#include <mma.h>
#include <math.h>

using namespace nvcuda;

// Problem constants (match reference setup_inputs)
#define NN 100000      // nodes
#define NE 1600000     // edges
#define NG 128         // graphs
#define INF 128
#define HF  128
#define OF  64
#define HID 10
#define NCLS 10

#define SCAN_NB ((NN + 1023) / 1024)   // 98 blocks for the node scan

// ---------------- scratch (device globals; allocation-free) ----------------
__device__ __align__(128) unsigned char  g_Y1f[(size_t)NN * 128]; // fp8 e4m3 (feats@W1), UNscaled
__device__ __align__(128) __nv_bfloat16 g_A1h[(size_t)NN * 128];  // bf16(relu(sI.*M1+b1)) = h1
__device__ __align__(128) __nv_bfloat16 g_Y2h[(size_t)NN * 64];   // bf16(sO .* (h1@W2))
__device__ int   g_degO[NN];
__device__ int   g_degI[NN];
__device__ float g_sO[NN];
__device__ float g_sI[NN];
__device__ int   g_rowoff[NN + 1];   // CSR row offsets (by dst)
__device__ int   g_cursor[NN];       // fill cursors
__device__ int   g_csrc[NE];         // CSR column indices = src per dst-sorted edge
__device__ unsigned long long g_look[128]; // decoupled-lookback state (flag|value)
__device__ float g_pooled[NG * 64];  // per-graph sums (atomics)

// ---------------- helpers ----------------
__device__ __forceinline__ float2 fp8x2_to_f2(unsigned short s) {
    __half2_raw h = __nv_cvt_fp8x2_to_halfraw2((__nv_fp8x2_storage_t)s, __NV_E4M3);
    return __half22float2(*reinterpret_cast<__half2*>(&h));
}

// ---------------- setup kernels ----------------
__global__ void zero_deg_kernel() {
    int i = blockIdx.x * 256 + threadIdx.x;
    if (i < NN) { g_degO[i] = 0; g_degI[i] = 0; }
    if (i < NG * 64) g_pooled[i] = 0.f;
    if (i < 128) g_look[i] = 0ull;
}

__global__ void degree_kernel(const int* __restrict__ src, const int* __restrict__ dst) {
    int i = blockIdx.x * 256 + threadIdx.x;
    if (i < NE) {
        atomicAdd(&g_degO[src[i]], 1);
        atomicAdd(&g_degI[dst[i]], 1);
    }
}

// Single-kernel scan with decoupled lookback (98 blocks = one wave, all resident).
// Writes rowoff/cursor + normalization scales.
#define LOOK_AGG  (1ull << 62)
#define LOOK_PREF (1ull << 63)
__global__ void __launch_bounds__(1024) scan_fused() {
    int i = blockIdx.x * 1024 + threadIdx.x;
    int v = (i < NN) ? g_degI[i] : 0;
    __shared__ int ps[1024];
    __shared__ int s_ex;
    ps[threadIdx.x] = v;
    __syncthreads();
#pragma unroll
    for (int off = 1; off < 1024; off <<= 1) {
        int t = (threadIdx.x >= off) ? ps[threadIdx.x - off] : 0;
        __syncthreads();
        ps[threadIdx.x] += t;
        __syncthreads();
    }
    // publish this block's aggregate
    if (threadIdx.x == 1023)
        atomicExch(&g_look[blockIdx.x], LOOK_AGG | (unsigned long long)(unsigned)ps[1023]);
    // lookback: sum predecessor aggregates until an inclusive prefix is found
    if (threadIdx.x == 0) {
        int ex = 0;
        for (int b = blockIdx.x - 1; b >= 0; b--) {
            unsigned long long x;
            do { x = atomicAdd(&g_look[b], 0ull); } while (x == 0ull);
            ex += (int)(unsigned)(x & 0xFFFFFFFFull);
            if (x & LOOK_PREF) break;
        }
        s_ex = ex;
    }
    __syncthreads();
    int ex0 = s_ex;
    if (threadIdx.x == 1023) {
        atomicExch(&g_look[blockIdx.x],
                   LOOK_PREF | (unsigned long long)(unsigned)(ex0 + ps[1023]));
        if (blockIdx.x == SCAN_NB - 1) g_rowoff[NN] = ex0 + ps[1023];
    }
    if (i < NN) {
        int d = g_degI[i];
        int ex = ex0 + ps[threadIdx.x] - d;
        g_rowoff[i] = ex;
        g_cursor[i] = ex;
        g_sO[i] = rsqrtf(fmaxf((float)g_degO[i], 1.f));
        g_sI[i] = rsqrtf(fmaxf((float)d, 1.f));
    }
}

__global__ void fill_kernel(const int* __restrict__ src, const int* __restrict__ dst) {
    int e = blockIdx.x * 256 + threadIdx.x;
    if (e < NE) {
        int d = dst[e];
        int p = atomicAdd(&g_cursor[d], 1);
        g_csrc[p] = src[e];
    }
}

// ---------------- tf32 WMMA GEMMs ----------------
// Y1f[r] = fp8_e4m3((feats @ W1)[r])   -- UNscaled; sO applied in gather128.
// Independent of the CSR/degree chain -> runs on a side stream.
__global__ void __launch_bounds__(256) gemm1_kernel(const float* __restrict__ X,
                                                    const float* __restrict__ W) {
    __shared__ __align__(16) float As[128][36];   // reused as epilogue staging
    __shared__ __align__(16) float Bs[32][132];
    const int tid = threadIdx.x;
    const int lane = tid & 31;
    const int wid = tid >> 5;
    const int wm = wid & 3;        // 0..3  -> rows wm*32
    const int wn = wid >> 2;       // 0..1  -> cols wn*64
    const int row0 = blockIdx.x * 128;

    wmma::fragment<wmma::accumulator, 16, 16, 8, float> acc[2][4];
#pragma unroll
    for (int mi = 0; mi < 2; mi++)
#pragma unroll
        for (int nj = 0; nj < 4; nj++) wmma::fill_fragment(acc[mi][nj], 0.f);

    for (int k0 = 0; k0 < 128; k0 += 32) {
        // A tile: 128x32 floats = 1024 float4
#pragma unroll
        for (int i = 0; i < 4; i++) {
            int idx = tid + i * 256;
            int r = idx >> 3;
            int c4 = idx & 7;
            int g = row0 + r;
            float4 v = make_float4(0.f, 0.f, 0.f, 0.f);
            if (g < NN) v = *(const float4*)(X + (size_t)g * 128 + k0 + c4 * 4);
            *(float4*)&As[r][c4 * 4] = v;
        }
        // B tile: 32x128 floats
#pragma unroll
        for (int i = 0; i < 4; i++) {
            int idx = tid + i * 256;
            int r = idx >> 5;
            int c4 = idx & 31;
            *(float4*)&Bs[r][c4 * 4] = *(const float4*)(W + (size_t)(k0 + r) * 128 + c4 * 4);
        }
        __syncthreads();
#pragma unroll
        for (int kk = 0; kk < 32; kk += 8) {
            wmma::fragment<wmma::matrix_a, 16, 16, 8, wmma::precision::tf32, wmma::row_major> a0, a1;
            wmma::load_matrix_sync(a0, &As[wm * 32][kk], 36);
            wmma::load_matrix_sync(a1, &As[wm * 32 + 16][kk], 36);
#pragma unroll
            for (int e = 0; e < a0.num_elements; e++) {
                a0.x[e] = wmma::__float_to_tf32(a0.x[e]);
                a1.x[e] = wmma::__float_to_tf32(a1.x[e]);
            }
#pragma unroll
            for (int nj = 0; nj < 4; nj++) {
                wmma::fragment<wmma::matrix_b, 16, 16, 8, wmma::precision::tf32, wmma::row_major> b;
                wmma::load_matrix_sync(b, &Bs[kk][wn * 64 + nj * 16], 132);
#pragma unroll
                for (int e = 0; e < b.num_elements; e++) b.x[e] = wmma::__float_to_tf32(b.x[e]);
                wmma::mma_sync(acc[0][nj], a0, b, acc[0][nj]);
                wmma::mma_sync(acc[1][nj], a1, b, acc[1][nj]);
            }
        }
        __syncthreads();
    }
    // ---- epilogue: stage fp32 tile in smem (As reused), store fp8 e4m3 ----
    float* st = &As[0][0] + wid * 320;   // 16 rows x ld=20 per warp
    const int erow = lane >> 1;          // 2 lanes per row
    const int ecol = (lane & 1) * 8;     // 8 floats per lane
#pragma unroll
    for (int mi = 0; mi < 2; mi++) {
#pragma unroll
        for (int nj = 0; nj < 4; nj++) {
            wmma::store_matrix_sync(st, acc[mi][nj], 20, wmma::mem_row_major);
            __syncwarp();
            int r = row0 + wm * 32 + mi * 16 + erow;
            if (r < NN) {
                const float* p = st + erow * 20 + ecol;
                unsigned int e0 = (unsigned int)__nv_cvt_float2_to_fp8x2(
                    make_float2(p[0], p[1]), __NV_SATFINITE, __NV_E4M3);
                unsigned int e1 = (unsigned int)__nv_cvt_float2_to_fp8x2(
                    make_float2(p[2], p[3]), __NV_SATFINITE, __NV_E4M3);
                unsigned int e2 = (unsigned int)__nv_cvt_float2_to_fp8x2(
                    make_float2(p[4], p[5]), __NV_SATFINITE, __NV_E4M3);
                unsigned int e3 = (unsigned int)__nv_cvt_float2_to_fp8x2(
                    make_float2(p[6], p[7]), __NV_SATFINITE, __NV_E4M3);
                uint2 o;
                o.x = e0 | (e1 << 16);
                o.y = e2 | (e3 << 16);
                *(uint2*)(g_Y1f + (size_t)r * 128 + wn * 64 + nj * 16 + ecol) = o;
            }
            __syncwarp();
        }
    }
}

// Y2h[r] = bf16(sO[r] * (A1h @ W2)[r]);  A1h is bf16 h1 (relu already applied).
__global__ void __launch_bounds__(256) gemm2_kernel(const float* __restrict__ W) {
    __shared__ __align__(16) float As[128][36];
    __shared__ __align__(16) float Bs[32][68];
    const int tid = threadIdx.x;
    const int lane = tid & 31;
    const int wid = tid >> 5;
    const int wm = wid & 3;        // rows wm*32
    const int wn = wid >> 2;       // cols wn*32
    const int row0 = blockIdx.x * 128;

    wmma::fragment<wmma::accumulator, 16, 16, 8, float> acc[2][2];
#pragma unroll
    for (int mi = 0; mi < 2; mi++)
#pragma unroll
        for (int nj = 0; nj < 2; nj++) wmma::fill_fragment(acc[mi][nj], 0.f);

    for (int k0 = 0; k0 < 128; k0 += 32) {
        // A tile: 128x32 bf16 -> fp32; 512 uint4 loads (8 bf16 each)
#pragma unroll
        for (int i = 0; i < 2; i++) {
            int idx = tid + i * 256;       // 0..511
            int r = idx >> 2;              // 4 uint4 per row-chunk
            int c8 = idx & 3;
            int g = row0 + r;
            float4 va = make_float4(0.f, 0.f, 0.f, 0.f);
            float4 vb = va;
            if (g < NN) {
                uint4 u = *(const uint4*)(g_A1h + (size_t)g * 128 + k0 + c8 * 8);
                float2 f0 = __bfloat1622float2(*(__nv_bfloat162*)&u.x);
                float2 f1 = __bfloat1622float2(*(__nv_bfloat162*)&u.y);
                float2 f2 = __bfloat1622float2(*(__nv_bfloat162*)&u.z);
                float2 f3 = __bfloat1622float2(*(__nv_bfloat162*)&u.w);
                va = make_float4(f0.x, f0.y, f1.x, f1.y);
                vb = make_float4(f2.x, f2.y, f3.x, f3.y);
            }
            *(float4*)&As[r][c8 * 8 + 0] = va;
            *(float4*)&As[r][c8 * 8 + 4] = vb;
        }
        // B tile: 32x64 floats = 512 float4
#pragma unroll
        for (int i = 0; i < 2; i++) {
            int idx = tid + i * 256;
            int r = idx >> 4;
            int c4 = idx & 15;
            *(float4*)&Bs[r][c4 * 4] = *(const float4*)(W + (size_t)(k0 + r) * 64 + c4 * 4);
        }
        __syncthreads();
#pragma unroll
        for (int kk = 0; kk < 32; kk += 8) {
            wmma::fragment<wmma::matrix_a, 16, 16, 8, wmma::precision::tf32, wmma::row_major> a0, a1;
            wmma::load_matrix_sync(a0, &As[wm * 32][kk], 36);
            wmma::load_matrix_sync(a1, &As[wm * 32 + 16][kk], 36);
#pragma unroll
            for (int e = 0; e < a0.num_elements; e++) {
                a0.x[e] = wmma::__float_to_tf32(a0.x[e]);
                a1.x[e] = wmma::__float_to_tf32(a1.x[e]);
            }
#pragma unroll
            for (int nj = 0; nj < 2; nj++) {
                wmma::fragment<wmma::matrix_b, 16, 16, 8, wmma::precision::tf32, wmma::row_major> b;
                wmma::load_matrix_sync(b, &Bs[kk][wn * 32 + nj * 16], 68);
#pragma unroll
                for (int e = 0; e < b.num_elements; e++) b.x[e] = wmma::__float_to_tf32(b.x[e]);
                wmma::mma_sync(acc[0][nj], a0, b, acc[0][nj]);
                wmma::mma_sync(acc[1][nj], a1, b, acc[1][nj]);
            }
        }
        __syncthreads();
    }
    // ---- epilogue: scale by sO, store bf16 ----
    float* st = &As[0][0] + wid * 320;
    const int erow = lane >> 1;
    const int ecol = (lane & 1) * 8;
#pragma unroll
    for (int mi = 0; mi < 2; mi++) {
#pragma unroll
        for (int nj = 0; nj < 2; nj++) {
            wmma::store_matrix_sync(st, acc[mi][nj], 20, wmma::mem_row_major);
            __syncwarp();
            int r = row0 + wm * 32 + mi * 16 + erow;
            if (r < NN) {
                float so = g_sO[r];
                __nv_bfloat16 h[8];
#pragma unroll
                for (int q = 0; q < 8; q++)
                    h[q] = __float2bfloat16(st[erow * 20 + ecol + q] * so);
                *(uint4*)(g_Y2h + (size_t)r * 64 + wn * 32 + nj * 16 + ecol) = *(uint4*)h;
            }
            __syncwarp();
        }
    }
}

// ---------------- CSR gather aggregation ----------------
// Layer 1: half-warp (16 lanes) per node; fp8 rows (128 B = 1 L2 line),
// lane loads uint2 = 8 fp8. Applies sO[src] per edge, then the full layer-1
// epilogue: A1h[n] = bf16(relu(sI[n]*sum + b1)).
__global__ void __launch_bounds__(256) gather128_kernel(const float* __restrict__ b1) {
    int t = blockIdx.x * 256 + threadIdx.x;
    int n = t >> 4;
    int lane = t & 15;
    if (n >= NN) return;
    int j = g_rowoff[n];
    int end = g_rowoff[n + 1];
    const uint2* Y = (const uint2*)g_Y1f;   // row = 16 uint2
    float acc[8];
#pragma unroll
    for (int q = 0; q < 8; q++) acc[q] = 0.f;

    for (; j + 3 < end; j += 4) {
        int s0 = g_csrc[j], s1 = g_csrc[j + 1], s2 = g_csrc[j + 2], s3 = g_csrc[j + 3];
        float c0 = g_sO[s0], c1 = g_sO[s1], c2 = g_sO[s2], c3 = g_sO[s3];
        uint2 u0 = Y[(size_t)s0 * 16 + lane];
        uint2 u1 = Y[(size_t)s1 * 16 + lane];
        uint2 u2 = Y[(size_t)s2 * 16 + lane];
        uint2 u3 = Y[(size_t)s3 * 16 + lane];
#pragma unroll
        for (int e = 0; e < 4; e++) {
            uint2 u = (e == 0) ? u0 : (e == 1) ? u1 : (e == 2) ? u2 : u3;
            float c = (e == 0) ? c0 : (e == 1) ? c1 : (e == 2) ? c2 : c3;
            float2 f0 = fp8x2_to_f2((unsigned short)(u.x & 0xFFFF));
            float2 f1 = fp8x2_to_f2((unsigned short)(u.x >> 16));
            float2 f2 = fp8x2_to_f2((unsigned short)(u.y & 0xFFFF));
            float2 f3 = fp8x2_to_f2((unsigned short)(u.y >> 16));
            acc[0] = fmaf(c, f0.x, acc[0]);
            acc[1] = fmaf(c, f0.y, acc[1]);
            acc[2] = fmaf(c, f1.x, acc[2]);
            acc[3] = fmaf(c, f1.y, acc[3]);
            acc[4] = fmaf(c, f2.x, acc[4]);
            acc[5] = fmaf(c, f2.y, acc[5]);
            acc[6] = fmaf(c, f3.x, acc[6]);
            acc[7] = fmaf(c, f3.y, acc[7]);
        }
    }
    for (; j < end; j++) {
        int s = g_csrc[j];
        float c = g_sO[s];
        uint2 u = Y[(size_t)s * 16 + lane];
        float2 f0 = fp8x2_to_f2((unsigned short)(u.x & 0xFFFF));
        float2 f1 = fp8x2_to_f2((unsigned short)(u.x >> 16));
        float2 f2 = fp8x2_to_f2((unsigned short)(u.y & 0xFFFF));
        float2 f3 = fp8x2_to_f2((unsigned short)(u.y >> 16));
        acc[0] = fmaf(c, f0.x, acc[0]);
        acc[1] = fmaf(c, f0.y, acc[1]);
        acc[2] = fmaf(c, f1.x, acc[2]);
        acc[3] = fmaf(c, f1.y, acc[3]);
        acc[4] = fmaf(c, f2.x, acc[4]);
        acc[5] = fmaf(c, f2.y, acc[5]);
        acc[6] = fmaf(c, f3.x, acc[6]);
        acc[7] = fmaf(c, f3.y, acc[7]);
    }
    // Layer-1 epilogue fused: h1 = relu(sI*sum + b1), stored bf16.
    float si = g_sI[n];
    __nv_bfloat16 h[8];
#pragma unroll
    for (int q = 0; q < 8; q++) {
        float v = fmaf(acc[q], si, b1[lane * 8 + q]);
        h[q] = __float2bfloat16(fmaxf(v, 0.f));
    }
    *(uint4*)(g_A1h + (size_t)n * 128 + lane * 8) = *(uint4*)h;
}

// Layer 2 aggregation fused with pooling: 8 lanes per node; computes the node's
// final features relu(sI*sum + b2) in-register and reduces into per-graph sums
// via a block-local smem stage (gid-sorted nodes). No M2 array, no pool kernel.
__global__ void __launch_bounds__(256) gather64_pool_kernel(const int* __restrict__ gids,
                                                            const float* __restrict__ b2) {
    __shared__ float sacc[4][64];
    {
        int s = threadIdx.x >> 6, c = threadIdx.x & 63;
        sacc[s][c] = 0.f;
    }
    __syncthreads();

    int t = blockIdx.x * 256 + threadIdx.x;
    int n = t >> 3;
    int lane = t & 7;
    int n0 = blockIdx.x * 32;           // first node of this block
    int g0 = gids[n0 < NN ? n0 : NN - 1];

    if (n < NN) {
        int j = g_rowoff[n];
        int end = g_rowoff[n + 1];
        const uint4* Y = (const uint4*)g_Y2h;   // row = 8 uint4
        float acc[8];
#pragma unroll
        for (int q = 0; q < 8; q++) acc[q] = 0.f;

        for (; j + 3 < end; j += 4) {
            int s0 = g_csrc[j], s1 = g_csrc[j + 1], s2 = g_csrc[j + 2], s3 = g_csrc[j + 3];
            uint4 v0 = Y[(size_t)s0 * 8 + lane];
            uint4 v1 = Y[(size_t)s1 * 8 + lane];
            uint4 v2 = Y[(size_t)s2 * 8 + lane];
            uint4 v3 = Y[(size_t)s3 * 8 + lane];
            const __nv_bfloat162* p0 = (const __nv_bfloat162*)&v0;
            const __nv_bfloat162* p1 = (const __nv_bfloat162*)&v1;
            const __nv_bfloat162* p2 = (const __nv_bfloat162*)&v2;
            const __nv_bfloat162* p3 = (const __nv_bfloat162*)&v3;
#pragma unroll
            for (int q = 0; q < 4; q++) {
                float2 f0 = __bfloat1622float2(p0[q]);
                float2 f1 = __bfloat1622float2(p1[q]);
                float2 f2 = __bfloat1622float2(p2[q]);
                float2 f3 = __bfloat1622float2(p3[q]);
                acc[2 * q + 0] += (f0.x + f1.x) + (f2.x + f3.x);
                acc[2 * q + 1] += (f0.y + f1.y) + (f2.y + f3.y);
            }
        }
        for (; j < end; j++) {
            int s = g_csrc[j];
            uint4 v = Y[(size_t)s * 8 + lane];
            const __nv_bfloat162* p = (const __nv_bfloat162*)&v;
#pragma unroll
            for (int q = 0; q < 4; q++) {
                float2 f = __bfloat1622float2(p[q]);
                acc[2 * q + 0] += f.x;
                acc[2 * q + 1] += f.y;
            }
        }
        // Node epilogue + pooling accumulation
        float si = g_sI[n];
        int gid = gids[n];
        int slot = gid - g0;
#pragma unroll
        for (int q = 0; q < 8; q++) {
            float v = fmaxf(fmaf(acc[q], si, b2[lane * 8 + q]), 0.f);
            if (slot < 4) atomicAdd(&sacc[slot][lane * 8 + q], v);
            else          atomicAdd(&g_pooled[gid * 64 + lane * 8 + q], v);
        }
    }
    __syncthreads();
    int slot = threadIdx.x >> 6, col = threadIdx.x & 63;
    int gg = g0 + slot;
    float v = sacc[slot][col];
    if (gg < NG && v != 0.f) atomicAdd(&g_pooled[gg * 64 + col], v);
}

// ---------------- head: per-graph mean + MLP + softmax ----------------
__global__ void __launch_bounds__(128) head_kernel(const int* __restrict__ gids,
                                                   const float* __restrict__ fcW1,
                                                   const float* __restrict__ fcb1,
                                                   const float* __restrict__ fcW2,
                                                   const float* __restrict__ fcb2,
                                                   float* __restrict__ out) {
    __shared__ float w1s[OF * HID];
    __shared__ float w2s[HID * NCLS];
    for (int i = threadIdx.x; i < OF * HID; i += blockDim.x) w1s[i] = fcW1[i];
    for (int i = threadIdx.x; i < HID * NCLS; i += blockDim.x) w2s[i] = fcW2[i];
    __syncthreads();

    int g = threadIdx.x;
    if (g >= NG) return;

    // node count for graph g via binary search on sorted gids
    int lo = 0, hi = NN;
    while (lo < hi) { int mid = (lo + hi) >> 1; if (gids[mid] < g) lo = mid + 1; else hi = mid; }
    int start = lo;
    hi = NN;
    while (lo < hi) { int mid = (lo + hi) >> 1; if (gids[mid] < g + 1) lo = mid + 1; else hi = mid; }
    int cnt = lo - start;
    float inv_c = 1.f / (float)(cnt > 0 ? cnt : 1);

    float x[OF];
#pragma unroll
    for (int c = 0; c < OF; c++) x[c] = g_pooled[g * 64 + c] * inv_c;
    float z[HID];
#pragma unroll
    for (int h = 0; h < HID; h++) {
        float s = fcb1[h];
#pragma unroll
        for (int c = 0; c < OF; c++) s = fmaf(x[c], w1s[c * HID + h], s);
        z[h] = fmaxf(s, 0.f);
    }
    float o[NCLS];
    float mx = -1e30f;
#pragma unroll
    for (int k = 0; k < NCLS; k++) {
        float s = fcb2[k];
#pragma unroll
        for (int h = 0; h < HID; h++) s = fmaf(z[h], w2s[h * NCLS + k], s);
        o[k] = s;
        mx = fmaxf(mx, s);
    }
    float sum = 0.f;
#pragma unroll
    for (int k = 0; k < NCLS; k++) { o[k] = expf(o[k] - mx); sum += o[k]; }
    float inv = 1.f / sum;
#pragma unroll
    for (int k = 0; k < NCLS; k++) out[g * NCLS + k] = o[k] * inv;
}

// ---------------- launch ----------------
extern "C" void kernel_launch(void* const* d_in, const int* in_sizes, int n_in,
                              void* d_out, int out_size) {
    const float* feats = (const float*)d_in[0];
    const int*   src   = (const int*)d_in[1];
    const int*   dst   = (const int*)d_in[2];
    const int*   gids  = (const int*)d_in[3];
    const float* W1    = (const float*)d_in[4];
    const float* b1    = (const float*)d_in[5];
    const float* W2    = (const float*)d_in[6];
    const float* b2    = (const float*)d_in[7];
    const float* fcW1  = (const float*)d_in[8];
    const float* fcb1  = (const float*)d_in[9];
    const float* fcW2  = (const float*)d_in[10];
    const float* fcb2  = (const float*)d_in[11];
    float* out = (float*)d_out;

    // Side stream + fork/join events (created once on the non-capturing
    // correctness call; reused during capture). Identical launches every call.
    static cudaStream_t s2 = nullptr;
    static cudaEvent_t evFork = nullptr, evJoin = nullptr;
    if (s2 == nullptr) {
        cudaStreamCreateWithFlags(&s2, cudaStreamNonBlocking);
        cudaEventCreateWithFlags(&evFork, cudaEventDisableTiming);
        cudaEventCreateWithFlags(&evJoin, cudaEventDisableTiming);
    }

    // Fork point recorded first: gemm1 (on s2) has no deps on the CSR chain,
    // so it executes concurrently with it regardless of submission order.
    cudaEventRecord(evFork, 0);

    // Main stream: degrees, CSR row offsets (single lookback scan), scales, fill
    zero_deg_kernel<<<(NN + 255) / 256, 256>>>();
    degree_kernel<<<(NE + 255) / 256, 256>>>(src, dst);
    scan_fused<<<SCAN_NB, 1024>>>();
    fill_kernel<<<(NE + 255) / 256, 256>>>(src, dst);

    // Side stream: Y1f = fp8(feats @ W1), unscaled
    cudaStreamWaitEvent(s2, evFork, 0);
    gemm1_kernel<<<(NN + 127) / 128, 256, 0, s2>>>(feats, W1);
    cudaEventRecord(evJoin, s2);

    // Join: gather needs both Y1f (s2) and the CSR (main stream).
    cudaStreamWaitEvent(0, evJoin, 0);

    // Layer 1 aggregation + epilogue fused: A1h = bf16(relu(sI .* (A·sO·Y1) + b1))
    gather128_kernel<<<(NN * 16 + 255) / 256, 256>>>(b1);

    // Layer 2 GEMM: Y2h = bf16(sO .* (A1h @ W2))
    gemm2_kernel<<<(NN + 127) / 128, 256>>>(W2);

    // Layer 2 aggregation + node epilogue + per-graph pooling (fused)
    gather64_pool_kernel<<<(NN * 8 + 255) / 256, 256>>>(gids, b2);

    // Head: mean (counts via binary search) + MLP + softmax
    head_kernel<<<1, 128>>>(gids, fcW1, fcb1, fcW2, fcb2, out);
}